// round 1
// baseline (speedup 1.0000x reference)
#include <cuda_runtime.h>
#include <math.h>

// Problem constants (fixed by reference setup_inputs)
#define T_TOK   8192
#define DIM     1024
#define HEADS   16
#define HD      64
#define SEQ     1024
#define BATCH   8
#define QKV_COLS 3072
#define EPSF 1.1920928955078125e-07f

// Scratch (device globals — no allocation allowed)
__device__ float g_qkv[(size_t)T_TOK * QKV_COLS];   // [T,3,H,D] — 100.7 MB
__device__ float g_attn[(size_t)T_TOK * DIM];       // [T,H,D]   — 33.6 MB

// ---------------------------------------------------------------------------
// GEMM  C[M,N] = A[M,K] @ B[N,K]^T   (both operands K-major, row-major)
// 128x128 block tile, BK=16, 256 threads, 8x8 register tile per thread.
// ---------------------------------------------------------------------------
#define GPAD 132
__global__ __launch_bounds__(256) void gemm_nt_kernel(
    const float* __restrict__ A, const float* __restrict__ B,
    float* __restrict__ C, int M, int N, int K)
{
    __shared__ float As[16 * GPAD];
    __shared__ float Bs[16 * GPAD];
    const int tid = threadIdx.x;
    const int ty = tid >> 4, tx = tid & 15;
    const int bm = blockIdx.y * 128, bn = blockIdx.x * 128;

    float acc[8][8];
#pragma unroll
    for (int i = 0; i < 8; ++i)
#pragma unroll
        for (int j = 0; j < 8; ++j) acc[i][j] = 0.f;

    for (int k0 = 0; k0 < K; k0 += 16) {
#pragma unroll
        for (int it = 0; it < 2; ++it) {
            int slot = tid + it * 256;      // 0..511
            int row = slot >> 2;            // 0..127
            int kq  = (slot & 3) * 4;       // 0,4,8,12
            float4 av = *(const float4*)(A + (size_t)(bm + row) * K + k0 + kq);
            As[(kq + 0) * GPAD + row] = av.x;
            As[(kq + 1) * GPAD + row] = av.y;
            As[(kq + 2) * GPAD + row] = av.z;
            As[(kq + 3) * GPAD + row] = av.w;
            float4 bv = *(const float4*)(B + (size_t)(bn + row) * K + k0 + kq);
            Bs[(kq + 0) * GPAD + row] = bv.x;
            Bs[(kq + 1) * GPAD + row] = bv.y;
            Bs[(kq + 2) * GPAD + row] = bv.z;
            Bs[(kq + 3) * GPAD + row] = bv.w;
        }
        __syncthreads();
#pragma unroll
        for (int kk = 0; kk < 16; ++kk) {
            float a[8], b[8];
            *(float4*)(a)     = *(const float4*)&As[kk * GPAD + ty * 8];
            *(float4*)(a + 4) = *(const float4*)&As[kk * GPAD + ty * 8 + 4];
            *(float4*)(b)     = *(const float4*)&Bs[kk * GPAD + tx * 8];
            *(float4*)(b + 4) = *(const float4*)&Bs[kk * GPAD + tx * 8 + 4];
#pragma unroll
            for (int i = 0; i < 8; ++i)
#pragma unroll
                for (int j = 0; j < 8; ++j)
                    acc[i][j] = fmaf(a[i], b[j], acc[i][j]);
        }
        __syncthreads();
    }
#pragma unroll
    for (int i = 0; i < 8; ++i) {
        float* cp = C + (size_t)(bm + ty * 8 + i) * N + bn + tx * 8;
        *(float4*)(cp)     = make_float4(acc[i][0], acc[i][1], acc[i][2], acc[i][3]);
        *(float4*)(cp + 4) = make_float4(acc[i][4], acc[i][5], acc[i][6], acc[i][7]);
    }
}

// ---------------------------------------------------------------------------
// Fused RMSNorm + RoPE on q and k, in place in g_qkv. One block per token,
// 8 warps; each warp handles 2 heads x {q,k}. Lane owns elems d and d+32,
// which is exactly the rotate-half pairing.
// ---------------------------------------------------------------------------
__global__ __launch_bounds__(256) void rmsrope_kernel(
    float* __restrict__ qkv,
    const float* __restrict__ rope_cos, const float* __restrict__ rope_sin,
    const float* __restrict__ qw, const float* __restrict__ kw)
{
    const int t = blockIdx.x;
    const int warp = threadIdx.x >> 5, lane = threadIdx.x & 31;
    const float c1 = rope_cos[(size_t)t * HD + lane];
    const float c2 = rope_cos[(size_t)t * HD + 32 + lane];
    const float s1 = rope_sin[(size_t)t * HD + lane];
    const float s2 = rope_sin[(size_t)t * HD + 32 + lane];

#pragma unroll
    for (int hh = 0; hh < 2; ++hh) {
        const int h = warp * 2 + hh;
#pragma unroll
        for (int qk = 0; qk < 2; ++qk) {
            float* p = qkv + (size_t)t * QKV_COLS + qk * DIM + h * HD;
            float x1 = p[lane], x2 = p[lane + 32];
            float ss = x1 * x1 + x2 * x2;
#pragma unroll
            for (int off = 16; off; off >>= 1)
                ss += __shfl_xor_sync(0xffffffffu, ss, off);
            const float r = rsqrtf(ss * (1.f / 64.f) + EPSF);
            const float* w = qk ? kw : qw;
            const float n1 = x1 * r * w[lane];
            const float n2 = x2 * r * w[lane + 32];
            p[lane]      = n1 * c1 - n2 * s1;
            p[lane + 32] = n2 * c2 + n1 * s2;
        }
    }
}

// ---------------------------------------------------------------------------
// Flash attention, fp32. Block = 64 queries of one (b,h). 256 threads as a
// 16x16 grid; each thread owns a 4x4 tile of the 64x64 S/P tile and a 4x4
// tile of the 64(q) x 64(d) output accumulator. Q/K stored d-major in smem
// so the S-GEMM inner loop is two float4 LDS + 16 FMA per d.
// ---------------------------------------------------------------------------
#define APAD 68
#define ATT_SMEM (4 * 64 * APAD * 4)
__global__ __launch_bounds__(256) void attn_kernel(
    const float* __restrict__ qkv, float* __restrict__ out)
{
    extern __shared__ float sm[];
    float* Qs = sm;                  // [d][q]  64 x APAD
    float* Ks = Qs + 64 * APAD;      // [d][k]
    float* Vs = Ks + 64 * APAD;      // [k][d]
    float* Ps = Vs + 64 * APAD;      // [q][k]

    const int tid = threadIdx.x;
    const int ty = tid >> 4, tx = tid & 15;
    const int qc = blockIdx.x, h = blockIdx.y, b = blockIdx.z;
    const int q0 = qc * 64;
    const float scale = 0.125f;  // 64^-0.5

    // Load Q tile (scaled), transposed to d-major
    for (int slot = tid; slot < 64 * 16; slot += 256) {
        int r = slot >> 4, c4 = (slot & 15) * 4;
        const float* src = qkv + (size_t)(b * SEQ + q0 + r) * QKV_COLS + h * HD + c4;
        float4 v = *(const float4*)src;
        Qs[(c4 + 0) * APAD + r] = v.x * scale;
        Qs[(c4 + 1) * APAD + r] = v.y * scale;
        Qs[(c4 + 2) * APAD + r] = v.z * scale;
        Qs[(c4 + 3) * APAD + r] = v.w * scale;
    }

    float m[4], l[4], o[4][4];
#pragma unroll
    for (int i = 0; i < 4; ++i) {
        m[i] = -1e30f; l[i] = 0.f;
#pragma unroll
        for (int j = 0; j < 4; ++j) o[i][j] = 0.f;
    }

    for (int kb = 0; kb < SEQ / 64; ++kb) {
        __syncthreads();  // protect Ks/Vs/Ps reuse (and Qs on first iter)
        for (int slot = tid; slot < 64 * 16; slot += 256) {
            int r = slot >> 4, c4 = (slot & 15) * 4;
            const float* base = qkv + (size_t)(b * SEQ + kb * 64 + r) * QKV_COLS + h * HD;
            float4 kv = *(const float4*)(base + DIM + c4);
            Ks[(c4 + 0) * APAD + r] = kv.x;
            Ks[(c4 + 1) * APAD + r] = kv.y;
            Ks[(c4 + 2) * APAD + r] = kv.z;
            Ks[(c4 + 3) * APAD + r] = kv.w;
            *(float4*)&Vs[r * APAD + c4] = *(const float4*)(base + 2 * DIM + c4);
        }
        __syncthreads();

        // S = Q K^T (scaled)
        float s[4][4];
#pragma unroll
        for (int i = 0; i < 4; ++i)
#pragma unroll
            for (int j = 0; j < 4; ++j) s[i][j] = 0.f;
#pragma unroll 16
        for (int d = 0; d < 64; ++d) {
            float4 a = *(const float4*)&Qs[d * APAD + ty * 4];
            float4 bb = *(const float4*)&Ks[d * APAD + tx * 4];
            const float av[4] = {a.x, a.y, a.z, a.w};
            const float bv[4] = {bb.x, bb.y, bb.z, bb.w};
#pragma unroll
            for (int i = 0; i < 4; ++i)
#pragma unroll
                for (int j = 0; j < 4; ++j)
                    s[i][j] = fmaf(av[i], bv[j], s[i][j]);
        }

        // Online softmax per row (16-lane groups along tx)
#pragma unroll
        for (int i = 0; i < 4; ++i) {
            float mx = fmaxf(fmaxf(s[i][0], s[i][1]), fmaxf(s[i][2], s[i][3]));
#pragma unroll
            for (int off = 8; off; off >>= 1)
                mx = fmaxf(mx, __shfl_xor_sync(0xffffffffu, mx, off));
            const float newm = fmaxf(m[i], mx);
            const float corr = __expf(m[i] - newm);
            l[i] *= corr;
#pragma unroll
            for (int j = 0; j < 4; ++j) o[i][j] *= corr;
            float ls = 0.f;
#pragma unroll
            for (int j = 0; j < 4; ++j) {
                s[i][j] = __expf(s[i][j] - newm);
                ls += s[i][j];
            }
#pragma unroll
            for (int off = 8; off; off >>= 1)
                ls += __shfl_xor_sync(0xffffffffu, ls, off);
            l[i] += ls;
            m[i] = newm;
            *(float4*)&Ps[(ty * 4 + i) * APAD + tx * 4] =
                make_float4(s[i][0], s[i][1], s[i][2], s[i][3]);
        }
        __syncthreads();

        // O += P V
#pragma unroll 16
        for (int k = 0; k < 64; ++k) {
            float4 vv = *(const float4*)&Vs[k * APAD + tx * 4];
#pragma unroll
            for (int i = 0; i < 4; ++i) {
                const float p = Ps[(ty * 4 + i) * APAD + k];
                o[i][0] = fmaf(p, vv.x, o[i][0]);
                o[i][1] = fmaf(p, vv.y, o[i][1]);
                o[i][2] = fmaf(p, vv.z, o[i][2]);
                o[i][3] = fmaf(p, vv.w, o[i][3]);
            }
        }
    }

#pragma unroll
    for (int i = 0; i < 4; ++i) {
        const float inv = 1.f / l[i];
        float* dst = out + (size_t)(b * SEQ + q0 + ty * 4 + i) * DIM + h * HD + tx * 4;
        *(float4*)dst = make_float4(o[i][0] * inv, o[i][1] * inv,
                                    o[i][2] * inv, o[i][3] * inv);
    }
}

// ---------------------------------------------------------------------------
extern "C" void kernel_launch(void* const* d_in, const int* in_sizes, int n_in,
                              void* d_out, int out_size)
{
    // Identify inputs by element count (robust to scalar max_seqlen presence)
    const float *x = 0, *rc = 0, *rs = 0, *wqkv = 0, *wproj = 0, *qw = 0, *kw = 0;
    for (int i = 0; i < n_in; ++i) {
        const int s = in_sizes[i];
        if (s == T_TOK * DIM && !x)            x = (const float*)d_in[i];
        else if (s == T_TOK * HD)              { if (!rc) rc = (const float*)d_in[i];
                                                 else if (!rs) rs = (const float*)d_in[i]; }
        else if (s == QKV_COLS * DIM)          wqkv = (const float*)d_in[i];
        else if (s == DIM * DIM && !wproj)     wproj = (const float*)d_in[i];
        else if (s == HD)                      { if (!qw) qw = (const float*)d_in[i];
                                                 else if (!kw) kw = (const float*)d_in[i]; }
    }
    float* out = (float*)d_out;

    void *pqkv_v, *pattn_v;
    cudaGetSymbolAddress(&pqkv_v, g_qkv);
    cudaGetSymbolAddress(&pattn_v, g_attn);
    float* pqkv = (float*)pqkv_v;
    float* pattn = (float*)pattn_v;

    cudaFuncSetAttribute(attn_kernel,
                         cudaFuncAttributeMaxDynamicSharedMemorySize, ATT_SMEM);

    // 1) QKV = x @ w_qkv^T
    gemm_nt_kernel<<<dim3(QKV_COLS / 128, T_TOK / 128), 256>>>(
        x, wqkv, pqkv, T_TOK, QKV_COLS, DIM);
    // 2) RMSNorm + RoPE on q,k (in place)
    rmsrope_kernel<<<T_TOK, 256>>>(pqkv, rc, rs, qw, kw);
    // 3) Attention
    attn_kernel<<<dim3(SEQ / 64, HEADS, BATCH), 256, ATT_SMEM>>>(pqkv, pattn);
    // 4) out = attn @ w_proj^T
    gemm_nt_kernel<<<dim3(DIM / 128, T_TOK / 128), 256>>>(
        pattn, wproj, out, T_TOK, DIM, DIM);
}

// round 4
// speedup vs baseline: 1.5381x; 1.5381x over previous
#include <cuda_runtime.h>
#include <cuda_bf16.h>
#include <math.h>
#include <stdint.h>

// Problem constants (fixed by reference setup_inputs)
#define T_TOK   8192
#define DIM     1024
#define HEADS   16
#define HD      64
#define SEQ     1024
#define BATCH   8
#define QKV_COLS 3072
#define EPSF 1.1920928955078125e-07f

// Scratch (device globals — no allocation allowed)
__device__ float g_qkv[(size_t)T_TOK * QKV_COLS];               // [T,3,H,D] fp32
__device__ __nv_bfloat16 g_xhi[(size_t)T_TOK * DIM];
__device__ __nv_bfloat16 g_xlo[(size_t)T_TOK * DIM];
__device__ __nv_bfloat16 g_wqhi[(size_t)QKV_COLS * DIM];
__device__ __nv_bfloat16 g_wqlo[(size_t)QKV_COLS * DIM];
__device__ __nv_bfloat16 g_wphi[(size_t)DIM * DIM];
__device__ __nv_bfloat16 g_wplo[(size_t)DIM * DIM];
__device__ __nv_bfloat16 g_ahi[(size_t)T_TOK * DIM];
__device__ __nv_bfloat16 g_alo[(size_t)T_TOK * DIM];

// ===========================================================================
// fp32 -> (hi, lo) bf16 split:  hi = bf16(v), lo = bf16(v - hi)
// ===========================================================================
__global__ __launch_bounds__(256) void split_kernel(
    const float* __restrict__ src, __nv_bfloat16* __restrict__ hi,
    __nv_bfloat16* __restrict__ lo, int n4)
{
    const int i = blockIdx.x * 256 + threadIdx.x;
    if (i >= n4) return;
    const float4 v = ((const float4*)src)[i];
    __nv_bfloat16 h0 = __float2bfloat16_rn(v.x);
    __nv_bfloat16 h1 = __float2bfloat16_rn(v.y);
    __nv_bfloat16 h2 = __float2bfloat16_rn(v.z);
    __nv_bfloat16 h3 = __float2bfloat16_rn(v.w);
    __nv_bfloat162* hp = (__nv_bfloat162*)(hi) + i * 2;
    hp[0] = __nv_bfloat162(h0, h1);
    hp[1] = __nv_bfloat162(h2, h3);
    __nv_bfloat162* lp = (__nv_bfloat162*)(lo) + i * 2;
    lp[0] = __nv_bfloat162(__float2bfloat16_rn(v.x - __bfloat162float(h0)),
                           __float2bfloat16_rn(v.y - __bfloat162float(h1)));
    lp[1] = __nv_bfloat162(__float2bfloat16_rn(v.z - __bfloat162float(h2)),
                           __float2bfloat16_rn(v.w - __bfloat162float(h3)));
}

// ===========================================================================
// Split-bf16 GEMM:  C[M,N] = A[M,K=1024] @ B[N,K=1024]^T, fp32 out.
// A,B given as (hi,lo) bf16 pairs. 3-term: AhBh + AhBl + AlBh.
// 128x128 CTA tile, BK=64, 3-stage cp.async ring, 256 threads (8 warps),
// warp tile 64x32, m16n8k16 atoms. Smem rows padded to 144B (36 words).
// ===========================================================================
#define SROWB 144
#define TILEB (128 * SROWB)             // 18432 B
#define STAGEB (4 * TILEB)              // 73728 B (Ahi,Alo,Bhi,Blo)
#define GSMEM (3 * STAGEB)              // 221184 B

__device__ __forceinline__ uint32_t smem_u32(const void* p) {
    uint32_t a;
    asm("{ .reg .u64 t; cvta.to.shared.u64 t, %1; cvt.u32.u64 %0, t; }"
        : "=r"(a) : "l"(p));
    return a;
}
__device__ __forceinline__ void cpa16(uint32_t s, const void* g) {
    asm volatile("cp.async.cg.shared.global [%0], [%1], 16;" :: "r"(s), "l"(g));
}
__device__ __forceinline__ void mma_bf16(float* d, const uint32_t* a,
                                         const uint32_t* b) {
    asm volatile(
        "mma.sync.aligned.m16n8k16.row.col.f32.bf16.bf16.f32 "
        "{%0,%1,%2,%3}, {%4,%5,%6,%7}, {%8,%9}, {%0,%1,%2,%3};"
        : "+f"(d[0]), "+f"(d[1]), "+f"(d[2]), "+f"(d[3])
        : "r"(a[0]), "r"(a[1]), "r"(a[2]), "r"(a[3]), "r"(b[0]), "r"(b[1]));
}

__global__ __launch_bounds__(256, 1) void gemm_split_kernel(
    const __nv_bfloat16* __restrict__ Ahi, const __nv_bfloat16* __restrict__ Alo,
    const __nv_bfloat16* __restrict__ Bhi, const __nv_bfloat16* __restrict__ Blo,
    float* __restrict__ C, int Nstride)
{
    extern __shared__ char smc[];
    const int tid = threadIdx.x, wid = tid >> 5, lane = tid & 31;
    const int bm = blockIdx.y * 128, bn = blockIdx.x * 128;
    const int wm = (wid >> 2) * 64;      // warp row offset: 0 / 64
    const int wn = (wid & 3) * 32;       // warp col offset: 0..96
    const int lr = lane >> 2, lc = lane & 3;

    float acc[4][4][4];
#pragma unroll
    for (int i = 0; i < 4; ++i)
#pragma unroll
        for (int j = 0; j < 4; ++j)
#pragma unroll
            for (int r = 0; r < 4; ++r) acc[i][j][r] = 0.f;

    auto load_stage = [&](int s, int chunk) {
        char* base = smc + s * STAGEB;
        const int k0 = chunk * 64;
#pragma unroll
        for (int i = 0; i < 4; ++i) {
            const int idx = tid + i * 256;      // 0..1023
            const int row = idx >> 3;           // 0..127
            const int c = idx & 7;              // 16B chunk (8 bf16)
            const uint32_t so = (uint32_t)(row * SROWB + c * 16);
            const size_t ga = (size_t)(bm + row) * 1024 + k0 + c * 8;
            const size_t gb = (size_t)(bn + row) * 1024 + k0 + c * 8;
            cpa16(smem_u32(base + so), Ahi + ga);
            cpa16(smem_u32(base + TILEB + so), Alo + ga);
            cpa16(smem_u32(base + 2 * TILEB + so), Bhi + gb);
            cpa16(smem_u32(base + 3 * TILEB + so), Blo + gb);
        }
        asm volatile("cp.async.commit_group;" ::: "memory");
    };

    load_stage(0, 0);
    load_stage(1, 1);

    for (int c = 0; c < 16; ++c) {
        const int nc = c + 2;
        if (nc < 16) {
            load_stage(nc % 3, nc);
            asm volatile("cp.async.wait_group 1;" ::: "memory");
        } else {
            asm volatile("cp.async.wait_group 0;" ::: "memory");
        }
        __syncthreads();

        const uint32_t* AsH = (const uint32_t*)(smc + (c % 3) * STAGEB);
        const uint32_t* AsL = AsH + TILEB / 4;
        const uint32_t* BsH = AsH + 2 * TILEB / 4;
        const uint32_t* BsL = AsH + 3 * TILEB / 4;

#pragma unroll
        for (int ks = 0; ks < 4; ++ks) {
            const int kw = ks * 8;   // word offset within row (64 bf16 = 32 words)
            uint32_t ah[4][4], al[4][4], bh[4][2], bl[4][2];
#pragma unroll
            for (int mf = 0; mf < 4; ++mf) {
                const int r = wm + mf * 16 + lr;
                const int o0 = r * 36 + kw + lc, o1 = (r + 8) * 36 + kw + lc;
                ah[mf][0] = AsH[o0];     ah[mf][1] = AsH[o1];
                ah[mf][2] = AsH[o0 + 4]; ah[mf][3] = AsH[o1 + 4];
                al[mf][0] = AsL[o0];     al[mf][1] = AsL[o1];
                al[mf][2] = AsL[o0 + 4]; al[mf][3] = AsL[o1 + 4];
            }
#pragma unroll
            for (int nf = 0; nf < 4; ++nf) {
                const int n = wn + nf * 8 + lr;
                const int o = n * 36 + kw + lc;
                bh[nf][0] = BsH[o]; bh[nf][1] = BsH[o + 4];
                bl[nf][0] = BsL[o]; bl[nf][1] = BsL[o + 4];
            }
#pragma unroll
            for (int mf = 0; mf < 4; ++mf)
#pragma unroll
                for (int nf = 0; nf < 4; ++nf) {
                    mma_bf16(acc[mf][nf], ah[mf], bh[nf]);
                    mma_bf16(acc[mf][nf], ah[mf], bl[nf]);
                    mma_bf16(acc[mf][nf], al[mf], bh[nf]);
                }
        }
        __syncthreads();
    }

    // epilogue (c0,c1 -> row, c2,c3 -> row+8; cols 2lc,2lc+1)
#pragma unroll
    for (int mf = 0; mf < 4; ++mf) {
        const int r0 = bm + wm + mf * 16 + lr;
#pragma unroll
        for (int nf = 0; nf < 4; ++nf) {
            const int col = bn + wn + nf * 8 + lc * 2;
            *(float2*)(C + (size_t)r0 * Nstride + col) =
                make_float2(acc[mf][nf][0], acc[mf][nf][1]);
            *(float2*)(C + (size_t)(r0 + 8) * Nstride + col) =
                make_float2(acc[mf][nf][2], acc[mf][nf][3]);
        }
    }
}

// ---------------------------------------------------------------------------
// Fused RMSNorm + RoPE on q and k, in place in g_qkv.
// ---------------------------------------------------------------------------
__global__ __launch_bounds__(256) void rmsrope_kernel(
    float* __restrict__ qkv,
    const float* __restrict__ rope_cos, const float* __restrict__ rope_sin,
    const float* __restrict__ qw, const float* __restrict__ kw)
{
    const int t = blockIdx.x;
    const int warp = threadIdx.x >> 5, lane = threadIdx.x & 31;
    const float c1 = rope_cos[(size_t)t * HD + lane];
    const float c2 = rope_cos[(size_t)t * HD + 32 + lane];
    const float s1 = rope_sin[(size_t)t * HD + lane];
    const float s2 = rope_sin[(size_t)t * HD + 32 + lane];

#pragma unroll
    for (int hh = 0; hh < 2; ++hh) {
        const int h = warp * 2 + hh;
#pragma unroll
        for (int qk = 0; qk < 2; ++qk) {
            float* p = qkv + (size_t)t * QKV_COLS + qk * DIM + h * HD;
            float x1 = p[lane], x2 = p[lane + 32];
            float ss = x1 * x1 + x2 * x2;
#pragma unroll
            for (int off = 16; off; off >>= 1)
                ss += __shfl_xor_sync(0xffffffffu, ss, off);
            const float r = rsqrtf(ss * (1.f / 64.f) + EPSF);
            const float* w = qk ? kw : qw;
            const float n1 = x1 * r * w[lane];
            const float n2 = x2 * r * w[lane + 32];
            p[lane]      = n1 * c1 - n2 * s1;
            p[lane + 32] = n2 * c2 + n1 * s2;
        }
    }
}

// ---------------------------------------------------------------------------
// Flash attention, fp32 SIMT (unchanged math); epilogue now emits split-bf16
// (hi,lo) directly for the proj GEMM — saves an fp32 round trip.
// ---------------------------------------------------------------------------
#define APAD 68
#define ATT_SMEM (4 * 64 * APAD * 4)
__global__ __launch_bounds__(256) void attn_kernel(
    const float* __restrict__ qkv,
    __nv_bfloat16* __restrict__ ohi, __nv_bfloat16* __restrict__ olo)
{
    extern __shared__ float smf[];
    float* Qs = smf;                 // [d][q]
    float* Ks = Qs + 64 * APAD;      // [d][k]
    float* Vs = Ks + 64 * APAD;      // [k][d]
    float* Ps = Vs + 64 * APAD;      // [q][k]

    const int tid = threadIdx.x;
    const int ty = tid >> 4, tx = tid & 15;
    const int qc = blockIdx.x, h = blockIdx.y, b = blockIdx.z;
    const int q0 = qc * 64;
    const float scale = 0.125f;

    for (int slot = tid; slot < 64 * 16; slot += 256) {
        int r = slot >> 4, c4 = (slot & 15) * 4;
        const float* src = qkv + (size_t)(b * SEQ + q0 + r) * QKV_COLS + h * HD + c4;
        float4 v = *(const float4*)src;
        Qs[(c4 + 0) * APAD + r] = v.x * scale;
        Qs[(c4 + 1) * APAD + r] = v.y * scale;
        Qs[(c4 + 2) * APAD + r] = v.z * scale;
        Qs[(c4 + 3) * APAD + r] = v.w * scale;
    }

    float m[4], l[4], o[4][4];
#pragma unroll
    for (int i = 0; i < 4; ++i) {
        m[i] = -1e30f; l[i] = 0.f;
#pragma unroll
        for (int j = 0; j < 4; ++j) o[i][j] = 0.f;
    }

    for (int kb = 0; kb < SEQ / 64; ++kb) {
        __syncthreads();
        for (int slot = tid; slot < 64 * 16; slot += 256) {
            int r = slot >> 4, c4 = (slot & 15) * 4;
            const float* base = qkv + (size_t)(b * SEQ + kb * 64 + r) * QKV_COLS + h * HD;
            float4 kv = *(const float4*)(base + DIM + c4);
            Ks[(c4 + 0) * APAD + r] = kv.x;
            Ks[(c4 + 1) * APAD + r] = kv.y;
            Ks[(c4 + 2) * APAD + r] = kv.z;
            Ks[(c4 + 3) * APAD + r] = kv.w;
            *(float4*)&Vs[r * APAD + c4] = *(const float4*)(base + 2 * DIM + c4);
        }
        __syncthreads();

        float s[4][4];
#pragma unroll
        for (int i = 0; i < 4; ++i)
#pragma unroll
            for (int j = 0; j < 4; ++j) s[i][j] = 0.f;
#pragma unroll 16
        for (int d = 0; d < 64; ++d) {
            float4 a = *(const float4*)&Qs[d * APAD + ty * 4];
            float4 bb = *(const float4*)&Ks[d * APAD + tx * 4];
            const float av[4] = {a.x, a.y, a.z, a.w};
            const float bv[4] = {bb.x, bb.y, bb.z, bb.w};
#pragma unroll
            for (int i = 0; i < 4; ++i)
#pragma unroll
                for (int j = 0; j < 4; ++j)
                    s[i][j] = fmaf(av[i], bv[j], s[i][j]);
        }

#pragma unroll
        for (int i = 0; i < 4; ++i) {
            float mx = fmaxf(fmaxf(s[i][0], s[i][1]), fmaxf(s[i][2], s[i][3]));
#pragma unroll
            for (int off = 8; off; off >>= 1)
                mx = fmaxf(mx, __shfl_xor_sync(0xffffffffu, mx, off));
            const float newm = fmaxf(m[i], mx);
            const float corr = __expf(m[i] - newm);
            l[i] *= corr;
#pragma unroll
            for (int j = 0; j < 4; ++j) o[i][j] *= corr;
            float ls = 0.f;
#pragma unroll
            for (int j = 0; j < 4; ++j) {
                s[i][j] = __expf(s[i][j] - newm);
                ls += s[i][j];
            }
#pragma unroll
            for (int off = 8; off; off >>= 1)
                ls += __shfl_xor_sync(0xffffffffu, ls, off);
            l[i] += ls;
            m[i] = newm;
            *(float4*)&Ps[(ty * 4 + i) * APAD + tx * 4] =
                make_float4(s[i][0], s[i][1], s[i][2], s[i][3]);
        }
        __syncthreads();

#pragma unroll 16
        for (int k = 0; k < 64; ++k) {
            float4 vv = *(const float4*)&Vs[k * APAD + tx * 4];
#pragma unroll
            for (int i = 0; i < 4; ++i) {
                const float p = Ps[(ty * 4 + i) * APAD + k];
                o[i][0] = fmaf(p, vv.x, o[i][0]);
                o[i][1] = fmaf(p, vv.y, o[i][1]);
                o[i][2] = fmaf(p, vv.z, o[i][2]);
                o[i][3] = fmaf(p, vv.w, o[i][3]);
            }
        }
    }

#pragma unroll
    for (int i = 0; i < 4; ++i) {
        const float inv = 1.f / l[i];
        const size_t base = (size_t)(b * SEQ + q0 + ty * 4 + i) * DIM + h * HD + tx * 4;
        float v[4];
#pragma unroll
        for (int j = 0; j < 4; ++j) v[j] = o[i][j] * inv;
        __nv_bfloat16 hh[4], ll[4];
#pragma unroll
        for (int j = 0; j < 4; ++j) {
            hh[j] = __float2bfloat16_rn(v[j]);
            ll[j] = __float2bfloat16_rn(v[j] - __bfloat162float(hh[j]));
        }
        ((__nv_bfloat162*)(ohi + base))[0] = __nv_bfloat162(hh[0], hh[1]);
        ((__nv_bfloat162*)(ohi + base))[1] = __nv_bfloat162(hh[2], hh[3]);
        ((__nv_bfloat162*)(olo + base))[0] = __nv_bfloat162(ll[0], ll[1]);
        ((__nv_bfloat162*)(olo + base))[1] = __nv_bfloat162(ll[2], ll[3]);
    }
}

// ---------------------------------------------------------------------------
extern "C" void kernel_launch(void* const* d_in, const int* in_sizes, int n_in,
                              void* d_out, int out_size)
{
    const float *x = 0, *rc = 0, *rs = 0, *wqkv = 0, *wproj = 0, *qw = 0, *kw = 0;
    for (int i = 0; i < n_in; ++i) {
        const int s = in_sizes[i];
        if (s == T_TOK * DIM && !x)            x = (const float*)d_in[i];
        else if (s == T_TOK * HD)              { if (!rc) rc = (const float*)d_in[i];
                                                 else if (!rs) rs = (const float*)d_in[i]; }
        else if (s == QKV_COLS * DIM)          wqkv = (const float*)d_in[i];
        else if (s == DIM * DIM && !wproj)     wproj = (const float*)d_in[i];
        else if (s == HD)                      { if (!qw) qw = (const float*)d_in[i];
                                                 else if (!kw) kw = (const float*)d_in[i]; }
    }
    float* out = (float*)d_out;

    void *pqkv, *pxh, *pxl, *pwqh, *pwql, *pwph, *pwpl, *pah, *pal;
    cudaGetSymbolAddress(&pqkv, g_qkv);
    cudaGetSymbolAddress(&pxh, g_xhi);  cudaGetSymbolAddress(&pxl, g_xlo);
    cudaGetSymbolAddress(&pwqh, g_wqhi); cudaGetSymbolAddress(&pwql, g_wqlo);
    cudaGetSymbolAddress(&pwph, g_wphi); cudaGetSymbolAddress(&pwpl, g_wplo);
    cudaGetSymbolAddress(&pah, g_ahi);  cudaGetSymbolAddress(&pal, g_alo);

    cudaFuncSetAttribute(gemm_split_kernel,
                         cudaFuncAttributeMaxDynamicSharedMemorySize, GSMEM);
    cudaFuncSetAttribute(attn_kernel,
                         cudaFuncAttributeMaxDynamicSharedMemorySize, ATT_SMEM);

    // 0) fp32 -> (hi,lo) bf16 splits
    split_kernel<<<(T_TOK * DIM / 4 + 255) / 256, 256>>>(
        x, (__nv_bfloat16*)pxh, (__nv_bfloat16*)pxl, T_TOK * DIM / 4);
    split_kernel<<<(QKV_COLS * DIM / 4 + 255) / 256, 256>>>(
        wqkv, (__nv_bfloat16*)pwqh, (__nv_bfloat16*)pwql, QKV_COLS * DIM / 4);
    split_kernel<<<(DIM * DIM / 4 + 255) / 256, 256>>>(
        wproj, (__nv_bfloat16*)pwph, (__nv_bfloat16*)pwpl, DIM * DIM / 4);

    // 1) QKV = x @ w_qkv^T   (split-bf16 tensor cores)
    gemm_split_kernel<<<dim3(QKV_COLS / 128, T_TOK / 128), 256, GSMEM>>>(
        (__nv_bfloat16*)pxh, (__nv_bfloat16*)pxl,
        (__nv_bfloat16*)pwqh, (__nv_bfloat16*)pwql, (float*)pqkv, QKV_COLS);
    // 2) RMSNorm + RoPE on q,k (in place)
    rmsrope_kernel<<<T_TOK, 256>>>((float*)pqkv, rc, rs, qw, kw);
    // 3) Attention (fp32 flash; emits split-bf16 output)
    attn_kernel<<<dim3(SEQ / 64, HEADS, BATCH), 256, ATT_SMEM>>>(
        (float*)pqkv, (__nv_bfloat16*)pah, (__nv_bfloat16*)pal);
    // 4) out = attn @ w_proj^T   (split-bf16 tensor cores)
    gemm_split_kernel<<<dim3(DIM / 128, T_TOK / 128), 256, GSMEM>>>(
        (__nv_bfloat16*)pah, (__nv_bfloat16*)pal,
        (__nv_bfloat16*)pwph, (__nv_bfloat16*)pwpl, out, DIM);
}

// round 5
// speedup vs baseline: 2.4294x; 1.5794x over previous
#include <cuda_runtime.h>
#include <cuda_bf16.h>
#include <math.h>
#include <stdint.h>

// Problem constants (fixed by reference setup_inputs)
#define T_TOK   8192
#define DIM     1024
#define HEADS   16
#define HD      64
#define SEQ     1024
#define BATCH   8
#define QKV_COLS 3072
#define EPSF 1.1920928955078125e-07f

// Scratch (device globals — no allocation allowed)
__device__ float g_qkv[(size_t)T_TOK * QKV_COLS];               // [T,3,H,D] fp32
__device__ __nv_bfloat16 g_xhi[(size_t)T_TOK * DIM];
__device__ __nv_bfloat16 g_xlo[(size_t)T_TOK * DIM];
__device__ __nv_bfloat16 g_wqhi[(size_t)QKV_COLS * DIM];
__device__ __nv_bfloat16 g_wqlo[(size_t)QKV_COLS * DIM];
__device__ __nv_bfloat16 g_wphi[(size_t)DIM * DIM];
__device__ __nv_bfloat16 g_wplo[(size_t)DIM * DIM];
__device__ __nv_bfloat16 g_ahi[(size_t)T_TOK * DIM];
__device__ __nv_bfloat16 g_alo[(size_t)T_TOK * DIM];

// ===========================================================================
// Common helpers
// ===========================================================================
__device__ __forceinline__ uint32_t smem_u32(const void* p) {
    uint32_t a;
    asm("{ .reg .u64 t; cvta.to.shared.u64 t, %1; cvt.u32.u64 %0, t; }"
        : "=r"(a) : "l"(p));
    return a;
}
__device__ __forceinline__ void cpa16(uint32_t s, const void* g) {
    asm volatile("cp.async.cg.shared.global [%0], [%1], 16;" :: "r"(s), "l"(g));
}
__device__ __forceinline__ void mma_bf16(float* d, const uint32_t* a,
                                         const uint32_t* b) {
    asm volatile(
        "mma.sync.aligned.m16n8k16.row.col.f32.bf16.bf16.f32 "
        "{%0,%1,%2,%3}, {%4,%5,%6,%7}, {%8,%9}, {%0,%1,%2,%3};"
        : "+f"(d[0]), "+f"(d[1]), "+f"(d[2]), "+f"(d[3])
        : "r"(a[0]), "r"(a[1]), "r"(a[2]), "r"(a[3]), "r"(b[0]), "r"(b[1]));
}
__device__ __forceinline__ void ldsm4(uint32_t* r, uint32_t a) {
    asm volatile("ldmatrix.sync.aligned.m8n8.x4.shared.b16 {%0,%1,%2,%3}, [%4];"
        : "=r"(r[0]), "=r"(r[1]), "=r"(r[2]), "=r"(r[3]) : "r"(a));
}
__device__ __forceinline__ void ldsm4t(uint32_t* r, uint32_t a) {
    asm volatile("ldmatrix.sync.aligned.m8n8.x4.trans.shared.b16 {%0,%1,%2,%3}, [%4];"
        : "=r"(r[0]), "=r"(r[1]), "=r"(r[2]), "=r"(r[3]) : "r"(a));
}
__device__ __forceinline__ float ex2(float x) {
    float r; asm("ex2.approx.f32 %0, %1;" : "=f"(r) : "f"(x)); return r;
}
__device__ __forceinline__ uint32_t packbf(float lo, float hi) {
    uint32_t r;
    asm("cvt.rn.bf16x2.f32 %0, %1, %2;" : "=r"(r) : "f"(hi), "f"(lo));
    return r;
}
__device__ __forceinline__ float bfhi(float x) {
    return __bfloat162float(__float2bfloat16_rn(x));
}

// ===========================================================================
// fp32 -> (hi, lo) bf16 split
// ===========================================================================
__global__ __launch_bounds__(256) void split_kernel(
    const float* __restrict__ src, __nv_bfloat16* __restrict__ hi,
    __nv_bfloat16* __restrict__ lo, int n4)
{
    const int i = blockIdx.x * 256 + threadIdx.x;
    if (i >= n4) return;
    const float4 v = ((const float4*)src)[i];
    float h0 = bfhi(v.x), h1 = bfhi(v.y), h2 = bfhi(v.z), h3 = bfhi(v.w);
    uint32_t* hp = (uint32_t*)(hi) + i * 2;
    hp[0] = packbf(h0, h1);
    hp[1] = packbf(h2, h3);
    uint32_t* lp = (uint32_t*)(lo) + i * 2;
    lp[0] = packbf(v.x - h0, v.y - h1);
    lp[1] = packbf(v.z - h2, v.w - h3);
}

// ===========================================================================
// Split-bf16 GEMM with ldmatrix fragment loads.
// C[M,N] = A[M,K=1024] @ B[N,K=1024]^T, fp32 out. 3-term: AhBh + AhBl + AlBh.
// 128x128 CTA tile, BK=64, 3-stage cp.async ring, 256 threads (8 warps).
// ===========================================================================
#define SROWB 144
#define TILEB (128 * SROWB)             // 18432 B
#define STAGEB (4 * TILEB)              // 73728 B
#define GSMEM (3 * STAGEB)              // 221184 B

__global__ __launch_bounds__(256, 1) void gemm_split_kernel(
    const __nv_bfloat16* __restrict__ Ahi, const __nv_bfloat16* __restrict__ Alo,
    const __nv_bfloat16* __restrict__ Bhi, const __nv_bfloat16* __restrict__ Blo,
    float* __restrict__ C, int Nstride)
{
    extern __shared__ char smc[];
    const int tid = threadIdx.x, wid = tid >> 5, lane = tid & 31;
    const int bm = blockIdx.y * 128, bn = blockIdx.x * 128;
    const int wm = (wid >> 2) * 64;      // warp row offset: 0 / 64
    const int wn = (wid & 3) * 32;       // warp col offset: 0..96
    const int lr = lane >> 2, lc = lane & 3;
    const uint32_t sb0 = smem_u32(smc);
    const uint32_t ga_off =
        (uint32_t)((lane & 7) + ((lane >> 3) & 1) * 8) * SROWB +
        ((lane >> 4) & 1) * 16;
    const uint32_t gb_off =
        (uint32_t)((lane & 7) + ((lane >> 4) & 1) * 8) * SROWB +
        ((lane >> 3) & 1) * 16;

    float acc[4][4][4];
#pragma unroll
    for (int i = 0; i < 4; ++i)
#pragma unroll
        for (int j = 0; j < 4; ++j)
#pragma unroll
            for (int r = 0; r < 4; ++r) acc[i][j][r] = 0.f;

    auto load_stage = [&](int s, int chunk) {
        char* base = smc + s * STAGEB;
        const int k0 = chunk * 64;
#pragma unroll
        for (int i = 0; i < 4; ++i) {
            const int idx = tid + i * 256;      // 0..1023
            const int row = idx >> 3;           // 0..127
            const int c = idx & 7;              // 16B chunk (8 bf16)
            const uint32_t so = (uint32_t)(row * SROWB + c * 16);
            const size_t ga = (size_t)(bm + row) * 1024 + k0 + c * 8;
            const size_t gb = (size_t)(bn + row) * 1024 + k0 + c * 8;
            cpa16(smem_u32(base + so), Ahi + ga);
            cpa16(smem_u32(base + TILEB + so), Alo + ga);
            cpa16(smem_u32(base + 2 * TILEB + so), Bhi + gb);
            cpa16(smem_u32(base + 3 * TILEB + so), Blo + gb);
        }
        asm volatile("cp.async.commit_group;" ::: "memory");
    };

    load_stage(0, 0);
    load_stage(1, 1);

    for (int c = 0; c < 16; ++c) {
        const int nc = c + 2;
        if (nc < 16) {
            load_stage(nc % 3, nc);
            asm volatile("cp.async.wait_group 1;" ::: "memory");
        } else {
            asm volatile("cp.async.wait_group 0;" ::: "memory");
        }
        __syncthreads();

        const uint32_t sbase = sb0 + (c % 3) * STAGEB;
#pragma unroll
        for (int ks = 0; ks < 4; ++ks) {
            uint32_t ah[4][4], al[4][4], bh[2][4], bl[2][4];
#pragma unroll
            for (int mf = 0; mf < 4; ++mf) {
                ldsm4(ah[mf], sbase + (wm + mf * 16) * SROWB + ga_off + ks * 32);
                ldsm4(al[mf], sbase + TILEB + (wm + mf * 16) * SROWB + ga_off + ks * 32);
            }
#pragma unroll
            for (int np = 0; np < 2; ++np) {
                ldsm4(bh[np], sbase + 2 * TILEB + (wn + np * 16) * SROWB + gb_off + ks * 32);
                ldsm4(bl[np], sbase + 3 * TILEB + (wn + np * 16) * SROWB + gb_off + ks * 32);
            }
#pragma unroll
            for (int mf = 0; mf < 4; ++mf)
#pragma unroll
                for (int nf = 0; nf < 4; ++nf) {
                    const uint32_t* pbh = bh[nf >> 1] + (nf & 1) * 2;
                    const uint32_t* pbl = bl[nf >> 1] + (nf & 1) * 2;
                    mma_bf16(acc[mf][nf], ah[mf], pbh);
                    mma_bf16(acc[mf][nf], ah[mf], pbl);
                    mma_bf16(acc[mf][nf], al[mf], pbh);
                }
        }
        __syncthreads();
    }

    // epilogue (c0,c1 -> row lr, c2,c3 -> row lr+8; cols 2lc,2lc+1)
#pragma unroll
    for (int mf = 0; mf < 4; ++mf) {
        const int r0 = bm + wm + mf * 16 + lr;
#pragma unroll
        for (int nf = 0; nf < 4; ++nf) {
            const int col = bn + wn + nf * 8 + lc * 2;
            *(float2*)(C + (size_t)r0 * Nstride + col) =
                make_float2(acc[mf][nf][0], acc[mf][nf][1]);
            *(float2*)(C + (size_t)(r0 + 8) * Nstride + col) =
                make_float2(acc[mf][nf][2], acc[mf][nf][3]);
        }
    }
}

// ---------------------------------------------------------------------------
// Fused RMSNorm + RoPE on q and k, in place in g_qkv.
// ---------------------------------------------------------------------------
__global__ __launch_bounds__(256) void rmsrope_kernel(
    float* __restrict__ qkv,
    const float* __restrict__ rope_cos, const float* __restrict__ rope_sin,
    const float* __restrict__ qw, const float* __restrict__ kw)
{
    const int t = blockIdx.x;
    const int warp = threadIdx.x >> 5, lane = threadIdx.x & 31;
    const float c1 = rope_cos[(size_t)t * HD + lane];
    const float c2 = rope_cos[(size_t)t * HD + 32 + lane];
    const float s1 = rope_sin[(size_t)t * HD + lane];
    const float s2 = rope_sin[(size_t)t * HD + 32 + lane];

#pragma unroll
    for (int hh = 0; hh < 2; ++hh) {
        const int h = warp * 2 + hh;
#pragma unroll
        for (int qk = 0; qk < 2; ++qk) {
            float* p = qkv + (size_t)t * QKV_COLS + qk * DIM + h * HD;
            float x1 = p[lane], x2 = p[lane + 32];
            float ss = x1 * x1 + x2 * x2;
#pragma unroll
            for (int off = 16; off; off >>= 1)
                ss += __shfl_xor_sync(0xffffffffu, ss, off);
            const float r = rsqrtf(ss * (1.f / 64.f) + EPSF);
            const float* w = qk ? kw : qw;
            const float n1 = x1 * r * w[lane];
            const float n2 = x2 * r * w[lane + 32];
            p[lane]      = n1 * c1 - n2 * s1;
            p[lane + 32] = n2 * c2 + n1 * s2;
        }
    }
}

// ===========================================================================
// Flash attention, split-bf16 tensor cores.
// CTA = 128 queries of one (b,h); 8 warps, each owns 16 query rows.
// Q hi/lo fragments persistent in registers; per 64-key block K/V converted
// fp32 -> bf16 hi/lo in smem. S = QK^T 3-term; softmax in registers (exp2,
// log2e folded into scale); P packed hi/lo from accumulators; PV 3-term with
// V fragments via ldmatrix.trans. Emits split-bf16 output for proj GEMM.
// ===========================================================================
#define AROWB 144                        // 64 bf16 (128B) + 16B pad
// smem regions (bytes): during Q phase: Qhi 0..18432, Qlo 18432..36864
// during main loop:     Khi 0, Klo 9216, Vhi 18432, Vlo 27648
__global__ __launch_bounds__(256, 1) void attn_kernel(
    const float* __restrict__ qkv,
    __nv_bfloat16* __restrict__ ohi, __nv_bfloat16* __restrict__ olo)
{
    __shared__ __align__(128) char smb[36864];
    const uint32_t sb = smem_u32(smb);
    const int tid = threadIdx.x, wid = tid >> 5, lane = tid & 31;
    const int lr = lane >> 2, lc = lane & 3;
    const int h = blockIdx.y, b = blockIdx.z;
    const int q0 = blockIdx.x * 128;
    const int wq = wid * 16;
    const float sc = 0.125f * 1.4426950408889634f;   // D^-0.5 * log2(e)

    // --- Q: gmem fp32 -> smem bf16 hi/lo (scaled) ---
#pragma unroll
    for (int i = 0; i < 8; ++i) {
        const int slot = tid + i * 256;
        const int row = slot >> 4, c4 = (slot & 15) * 4;
        const float* src = qkv + (size_t)(b * SEQ + q0 + row) * QKV_COLS + h * HD + c4;
        float4 v = *(const float4*)src;
        v.x *= sc; v.y *= sc; v.z *= sc; v.w *= sc;
        const float h0 = bfhi(v.x), h1 = bfhi(v.y), h2 = bfhi(v.z), h3 = bfhi(v.w);
        uint32_t* dh = (uint32_t*)(smb + row * AROWB + c4 * 2);
        dh[0] = packbf(h0, h1); dh[1] = packbf(h2, h3);
        uint32_t* dl = (uint32_t*)(smb + 18432 + row * AROWB + c4 * 2);
        dl[0] = packbf(v.x - h0, v.y - h1); dl[1] = packbf(v.z - h2, v.w - h3);
    }
    __syncthreads();

    // --- Q fragments (persistent) ---
    const uint32_t a_off =
        (uint32_t)((lane & 7) + ((lane >> 3) & 1) * 8) * AROWB + ((lane >> 4) & 1) * 16;
    const uint32_t b_off =
        (uint32_t)((lane & 7) + ((lane >> 4) & 1) * 8) * AROWB + ((lane >> 3) & 1) * 16;
    const uint32_t v_off =
        (uint32_t)(lane & 15) * AROWB + ((lane >> 4) & 1) * 16;
    uint32_t qh[4][4], ql[4][4];
#pragma unroll
    for (int ks = 0; ks < 4; ++ks) {
        ldsm4(qh[ks], sb + wq * AROWB + a_off + ks * 32);
        ldsm4(ql[ks], sb + 18432 + wq * AROWB + a_off + ks * 32);
    }
    __syncthreads();   // Q smem region now free for K/V

    float m0 = -1e30f, m1 = -1e30f, l0 = 0.f, l1 = 0.f;
    float o[8][4];
#pragma unroll
    for (int nf = 0; nf < 8; ++nf)
#pragma unroll
        for (int r = 0; r < 4; ++r) o[nf][r] = 0.f;

    for (int kb = 0; kb < 16; ++kb) {
        // --- K,V: gmem fp32 -> smem bf16 hi/lo ---
#pragma unroll
        for (int i = 0; i < 4; ++i) {
            const int slot = tid + i * 256;
            const int row = slot >> 4, c4 = (slot & 15) * 4;
            const float* kp =
                qkv + (size_t)(b * SEQ + kb * 64 + row) * QKV_COLS + DIM + h * HD + c4;
            const float4 kv = *(const float4*)kp;
            const float4 vv = *(const float4*)(kp + DIM);
            const float kh0 = bfhi(kv.x), kh1 = bfhi(kv.y),
                        kh2 = bfhi(kv.z), kh3 = bfhi(kv.w);
            const float vh0 = bfhi(vv.x), vh1 = bfhi(vv.y),
                        vh2 = bfhi(vv.z), vh3 = bfhi(vv.w);
            uint32_t* d;
            d = (uint32_t*)(smb + row * AROWB + c4 * 2);            // Khi
            d[0] = packbf(kh0, kh1); d[1] = packbf(kh2, kh3);
            d = (uint32_t*)(smb + 9216 + row * AROWB + c4 * 2);     // Klo
            d[0] = packbf(kv.x - kh0, kv.y - kh1);
            d[1] = packbf(kv.z - kh2, kv.w - kh3);
            d = (uint32_t*)(smb + 18432 + row * AROWB + c4 * 2);    // Vhi
            d[0] = packbf(vh0, vh1); d[1] = packbf(vh2, vh3);
            d = (uint32_t*)(smb + 27648 + row * AROWB + c4 * 2);    // Vlo
            d[0] = packbf(vv.x - vh0, vv.y - vh1);
            d[1] = packbf(vv.z - vh2, vv.w - vh3);
        }
        __syncthreads();

        // --- S = Q K^T (3-term) ---
        float s[8][4];
#pragma unroll
        for (int nf = 0; nf < 8; ++nf)
#pragma unroll
            for (int r = 0; r < 4; ++r) s[nf][r] = 0.f;
#pragma unroll
        for (int ks = 0; ks < 4; ++ks)
#pragma unroll
            for (int np = 0; np < 4; ++np) {
                uint32_t bh[4], bl[4];
                ldsm4(bh, sb + np * 16 * AROWB + b_off + ks * 32);
                ldsm4(bl, sb + 9216 + np * 16 * AROWB + b_off + ks * 32);
                mma_bf16(s[2 * np],     qh[ks], bh);
                mma_bf16(s[2 * np],     qh[ks], bl);
                mma_bf16(s[2 * np],     ql[ks], bh);
                mma_bf16(s[2 * np + 1], qh[ks], bh + 2);
                mma_bf16(s[2 * np + 1], qh[ks], bl + 2);
                mma_bf16(s[2 * np + 1], ql[ks], bh + 2);
            }

        // --- online softmax (rows lr and lr+8; 4 lanes per row share lc) ---
        float mx0 = -1e30f, mx1 = -1e30f;
#pragma unroll
        for (int nf = 0; nf < 8; ++nf) {
            mx0 = fmaxf(mx0, fmaxf(s[nf][0], s[nf][1]));
            mx1 = fmaxf(mx1, fmaxf(s[nf][2], s[nf][3]));
        }
        mx0 = fmaxf(mx0, __shfl_xor_sync(0xffffffffu, mx0, 1));
        mx0 = fmaxf(mx0, __shfl_xor_sync(0xffffffffu, mx0, 2));
        mx1 = fmaxf(mx1, __shfl_xor_sync(0xffffffffu, mx1, 1));
        mx1 = fmaxf(mx1, __shfl_xor_sync(0xffffffffu, mx1, 2));
        const float nm0 = fmaxf(m0, mx0), nm1 = fmaxf(m1, mx1);
        const float cr0 = ex2(m0 - nm0), cr1 = ex2(m1 - nm1);
        m0 = nm0; m1 = nm1;
        float sum0 = 0.f, sum1 = 0.f;
#pragma unroll
        for (int nf = 0; nf < 8; ++nf) {
            s[nf][0] = ex2(s[nf][0] - nm0); sum0 += s[nf][0];
            s[nf][1] = ex2(s[nf][1] - nm0); sum0 += s[nf][1];
            s[nf][2] = ex2(s[nf][2] - nm1); sum1 += s[nf][2];
            s[nf][3] = ex2(s[nf][3] - nm1); sum1 += s[nf][3];
        }
        sum0 += __shfl_xor_sync(0xffffffffu, sum0, 1);
        sum0 += __shfl_xor_sync(0xffffffffu, sum0, 2);
        sum1 += __shfl_xor_sync(0xffffffffu, sum1, 1);
        sum1 += __shfl_xor_sync(0xffffffffu, sum1, 2);
        l0 = l0 * cr0 + sum0;
        l1 = l1 * cr1 + sum1;
#pragma unroll
        for (int nf = 0; nf < 8; ++nf) {
            o[nf][0] *= cr0; o[nf][1] *= cr0;
            o[nf][2] *= cr1; o[nf][3] *= cr1;
        }

        // --- pack P hi/lo into A-operand fragments ---
        uint32_t ph[4][4], pl[4][4];
#pragma unroll
        for (int ks = 0; ks < 4; ++ks) {
            const float p00 = s[2 * ks][0],     p01 = s[2 * ks][1];
            const float p10 = s[2 * ks][2],     p11 = s[2 * ks][3];
            const float p20 = s[2 * ks + 1][0], p21 = s[2 * ks + 1][1];
            const float p30 = s[2 * ks + 1][2], p31 = s[2 * ks + 1][3];
            const float h00 = bfhi(p00), h01 = bfhi(p01);
            const float h10 = bfhi(p10), h11 = bfhi(p11);
            const float h20 = bfhi(p20), h21 = bfhi(p21);
            const float h30 = bfhi(p30), h31 = bfhi(p31);
            ph[ks][0] = packbf(h00, h01); pl[ks][0] = packbf(p00 - h00, p01 - h01);
            ph[ks][1] = packbf(h10, h11); pl[ks][1] = packbf(p10 - h10, p11 - h11);
            ph[ks][2] = packbf(h20, h21); pl[ks][2] = packbf(p20 - h20, p21 - h21);
            ph[ks][3] = packbf(h30, h31); pl[ks][3] = packbf(p30 - h30, p31 - h31);
        }

        // --- O += P V (3-term), V frags via ldmatrix.trans ---
#pragma unroll
        for (int ks = 0; ks < 4; ++ks)
#pragma unroll
            for (int ng = 0; ng < 4; ++ng) {
                uint32_t vh[4], vl[4];
                ldsm4t(vh, sb + 18432 + ks * 2304 + v_off + ng * 32);
                ldsm4t(vl, sb + 27648 + ks * 2304 + v_off + ng * 32);
                mma_bf16(o[2 * ng],     ph[ks], vh);
                mma_bf16(o[2 * ng],     ph[ks], vl);
                mma_bf16(o[2 * ng],     pl[ks], vh);
                mma_bf16(o[2 * ng + 1], ph[ks], vh + 2);
                mma_bf16(o[2 * ng + 1], ph[ks], vl + 2);
                mma_bf16(o[2 * ng + 1], pl[ks], vh + 2);
            }
        __syncthreads();
    }

    // --- epilogue: normalize and emit split-bf16 ---
    const float i0 = 1.f / l0, i1 = 1.f / l1;
    const int t0 = b * SEQ + q0 + wq + lr;
#pragma unroll
    for (int nf = 0; nf < 8; ++nf) {
        const int col = h * HD + nf * 8 + lc * 2;
        const float v0 = o[nf][0] * i0, v1 = o[nf][1] * i0;
        const float h0 = bfhi(v0), h1 = bfhi(v1);
        ((uint32_t*)ohi)[((size_t)t0 * DIM + col) >> 1] = packbf(h0, h1);
        ((uint32_t*)olo)[((size_t)t0 * DIM + col) >> 1] = packbf(v0 - h0, v1 - h1);
        const float v2 = o[nf][2] * i1, v3 = o[nf][3] * i1;
        const float h2 = bfhi(v2), h3 = bfhi(v3);
        ((uint32_t*)ohi)[((size_t)(t0 + 8) * DIM + col) >> 1] = packbf(h2, h3);
        ((uint32_t*)olo)[((size_t)(t0 + 8) * DIM + col) >> 1] = packbf(v2 - h2, v3 - h3);
    }
}

// ---------------------------------------------------------------------------
extern "C" void kernel_launch(void* const* d_in, const int* in_sizes, int n_in,
                              void* d_out, int out_size)
{
    const float *x = 0, *rc = 0, *rs = 0, *wqkv = 0, *wproj = 0, *qw = 0, *kw = 0;
    for (int i = 0; i < n_in; ++i) {
        const int s = in_sizes[i];
        if (s == T_TOK * DIM && !x)            x = (const float*)d_in[i];
        else if (s == T_TOK * HD)              { if (!rc) rc = (const float*)d_in[i];
                                                 else if (!rs) rs = (const float*)d_in[i]; }
        else if (s == QKV_COLS * DIM)          wqkv = (const float*)d_in[i];
        else if (s == DIM * DIM && !wproj)     wproj = (const float*)d_in[i];
        else if (s == HD)                      { if (!qw) qw = (const float*)d_in[i];
                                                 else if (!kw) kw = (const float*)d_in[i]; }
    }
    float* out = (float*)d_out;

    void *pqkv, *pxh, *pxl, *pwqh, *pwql, *pwph, *pwpl, *pah, *pal;
    cudaGetSymbolAddress(&pqkv, g_qkv);
    cudaGetSymbolAddress(&pxh, g_xhi);  cudaGetSymbolAddress(&pxl, g_xlo);
    cudaGetSymbolAddress(&pwqh, g_wqhi); cudaGetSymbolAddress(&pwql, g_wqlo);
    cudaGetSymbolAddress(&pwph, g_wphi); cudaGetSymbolAddress(&pwpl, g_wplo);
    cudaGetSymbolAddress(&pah, g_ahi);  cudaGetSymbolAddress(&pal, g_alo);

    cudaFuncSetAttribute(gemm_split_kernel,
                         cudaFuncAttributeMaxDynamicSharedMemorySize, GSMEM);

    // 0) fp32 -> (hi,lo) bf16 splits
    split_kernel<<<(T_TOK * DIM / 4 + 255) / 256, 256>>>(
        x, (__nv_bfloat16*)pxh, (__nv_bfloat16*)pxl, T_TOK * DIM / 4);
    split_kernel<<<(QKV_COLS * DIM / 4 + 255) / 256, 256>>>(
        wqkv, (__nv_bfloat16*)pwqh, (__nv_bfloat16*)pwql, QKV_COLS * DIM / 4);
    split_kernel<<<(DIM * DIM / 4 + 255) / 256, 256>>>(
        wproj, (__nv_bfloat16*)pwph, (__nv_bfloat16*)pwpl, DIM * DIM / 4);

    // 1) QKV = x @ w_qkv^T
    gemm_split_kernel<<<dim3(QKV_COLS / 128, T_TOK / 128), 256, GSMEM>>>(
        (__nv_bfloat16*)pxh, (__nv_bfloat16*)pxl,
        (__nv_bfloat16*)pwqh, (__nv_bfloat16*)pwql, (float*)pqkv, QKV_COLS);
    // 2) RMSNorm + RoPE on q,k (in place)
    rmsrope_kernel<<<T_TOK, 256>>>((float*)pqkv, rc, rs, qw, kw);
    // 3) Attention (split-bf16 tensor cores; emits split-bf16 output)
    attn_kernel<<<dim3(SEQ / 128, HEADS, BATCH), 256>>>(
        (float*)pqkv, (__nv_bfloat16*)pah, (__nv_bfloat16*)pal);
    // 4) out = attn @ w_proj^T
    gemm_split_kernel<<<dim3(DIM / 128, T_TOK / 128), 256, GSMEM>>>(
        (__nv_bfloat16*)pah, (__nv_bfloat16*)pal,
        (__nv_bfloat16*)pwph, (__nv_bfloat16*)pwpl, out, DIM);
}

// round 6
// speedup vs baseline: 2.5133x; 1.0345x over previous
#include <cuda_runtime.h>
#include <cuda_bf16.h>
#include <math.h>
#include <stdint.h>

// Problem constants (fixed by reference setup_inputs)
#define T_TOK   8192
#define DIM     1024
#define HEADS   16
#define HD      64
#define SEQ     1024
#define BATCH   8
#define QKV_COLS 3072
#define EPSF 1.1920928955078125e-07f

// Scratch (device globals — no allocation allowed)
__device__ float g_qkv[(size_t)T_TOK * QKV_COLS];               // [T,3,H,D] fp32
__device__ __nv_bfloat16 g_xhi[(size_t)T_TOK * DIM];
__device__ __nv_bfloat16 g_xlo[(size_t)T_TOK * DIM];
__device__ __nv_bfloat16 g_wqhi[(size_t)QKV_COLS * DIM];
__device__ __nv_bfloat16 g_wqlo[(size_t)QKV_COLS * DIM];
__device__ __nv_bfloat16 g_wphi[(size_t)DIM * DIM];
__device__ __nv_bfloat16 g_wplo[(size_t)DIM * DIM];
__device__ __nv_bfloat16 g_ahi[(size_t)T_TOK * DIM];
__device__ __nv_bfloat16 g_alo[(size_t)T_TOK * DIM];

// ===========================================================================
// Common helpers
// ===========================================================================
__device__ __forceinline__ uint32_t smem_u32(const void* p) {
    uint32_t a;
    asm("{ .reg .u64 t; cvta.to.shared.u64 t, %1; cvt.u32.u64 %0, t; }"
        : "=r"(a) : "l"(p));
    return a;
}
__device__ __forceinline__ void cpa16(uint32_t s, const void* g) {
    asm volatile("cp.async.cg.shared.global [%0], [%1], 16;" :: "r"(s), "l"(g));
}
__device__ __forceinline__ void mma_bf16(float* d, const uint32_t* a,
                                         const uint32_t* b) {
    asm volatile(
        "mma.sync.aligned.m16n8k16.row.col.f32.bf16.bf16.f32 "
        "{%0,%1,%2,%3}, {%4,%5,%6,%7}, {%8,%9}, {%0,%1,%2,%3};"
        : "+f"(d[0]), "+f"(d[1]), "+f"(d[2]), "+f"(d[3])
        : "r"(a[0]), "r"(a[1]), "r"(a[2]), "r"(a[3]), "r"(b[0]), "r"(b[1]));
}
__device__ __forceinline__ void ldsm4(uint32_t* r, uint32_t a) {
    asm volatile("ldmatrix.sync.aligned.m8n8.x4.shared.b16 {%0,%1,%2,%3}, [%4];"
        : "=r"(r[0]), "=r"(r[1]), "=r"(r[2]), "=r"(r[3]) : "r"(a));
}
__device__ __forceinline__ void ldsm4t(uint32_t* r, uint32_t a) {
    asm volatile("ldmatrix.sync.aligned.m8n8.x4.trans.shared.b16 {%0,%1,%2,%3}, [%4];"
        : "=r"(r[0]), "=r"(r[1]), "=r"(r[2]), "=r"(r[3]) : "r"(a));
}
__device__ __forceinline__ float ex2(float x) {
    float r; asm("ex2.approx.f32 %0, %1;" : "=f"(r) : "f"(x)); return r;
}
__device__ __forceinline__ uint32_t packbf(float lo, float hi) {
    uint32_t r;
    asm("cvt.rn.bf16x2.f32 %0, %1, %2;" : "=r"(r) : "f"(hi), "f"(lo));
    return r;
}
__device__ __forceinline__ float bfhi(float x) {
    return __bfloat162float(__float2bfloat16_rn(x));
}

// ===========================================================================
// fp32 -> (hi, lo) bf16 split
// ===========================================================================
__global__ __launch_bounds__(256) void split_kernel(
    const float* __restrict__ src, __nv_bfloat16* __restrict__ hi,
    __nv_bfloat16* __restrict__ lo, int n4)
{
    const int i = blockIdx.x * 256 + threadIdx.x;
    if (i >= n4) return;
    const float4 v = ((const float4*)src)[i];
    float h0 = bfhi(v.x), h1 = bfhi(v.y), h2 = bfhi(v.z), h3 = bfhi(v.w);
    uint32_t* hp = (uint32_t*)(hi) + i * 2;
    hp[0] = packbf(h0, h1);
    hp[1] = packbf(h2, h3);
    uint32_t* lp = (uint32_t*)(lo) + i * 2;
    lp[0] = packbf(v.x - h0, v.y - h1);
    lp[1] = packbf(v.z - h2, v.w - h3);
}

// ===========================================================================
// Split-bf16 GEMM, 2 CTAs/SM.  C[M,N] = A[M,K=1024] @ B[N,K=1024]^T.
// 3-term: AhBh + AhBl + AlBh, terms separated to break accumulator chains.
// 128x128 CTA tile, BK=32; hi/lo packed per 144B smem row:
//   row r: [0,64) = hi k-chunk, [64,128) = lo k-chunk, [128,144) pad.
// 3-stage cp.async ring. 256 threads (8 warps, 64x32 warp tiles).
// ===========================================================================
#define SROWB 144
#define REG_B 18432                     // B region offset within stage
#define STAGEB 36864                    // A(128*144) + B(128*144)
#define GSMEM (3 * STAGEB)              // 110592 B -> 2 CTAs/SM

__global__ __launch_bounds__(256, 2) void gemm_split_kernel(
    const __nv_bfloat16* __restrict__ Ahi, const __nv_bfloat16* __restrict__ Alo,
    const __nv_bfloat16* __restrict__ Bhi, const __nv_bfloat16* __restrict__ Blo,
    float* __restrict__ C, int Nstride)
{
    extern __shared__ char smc[];
    const int tid = threadIdx.x, wid = tid >> 5, lane = tid & 31;
    const int bm = blockIdx.y * 128, bn = blockIdx.x * 128;
    const int wm = (wid >> 2) * 64;      // warp row offset: 0 / 64
    const int wn = (wid & 3) * 32;       // warp col offset: 0..96
    const int lr = lane >> 2, lc = lane & 3;
    const uint32_t sb0 = smem_u32(smc);
    const uint32_t ga_off =
        (uint32_t)((lane & 7) + ((lane >> 3) & 1) * 8) * SROWB +
        ((lane >> 4) & 1) * 16;
    const uint32_t gb_off =
        (uint32_t)((lane & 7) + ((lane >> 4) & 1) * 8) * SROWB +
        ((lane >> 3) & 1) * 16;

    float acc[4][4][4];
#pragma unroll
    for (int i = 0; i < 4; ++i)
#pragma unroll
        for (int j = 0; j < 4; ++j)
#pragma unroll
            for (int r = 0; r < 4; ++r) acc[i][j][r] = 0.f;

    // per-stage load: 2048 x 16B. groups: 0-1 Ahi, 2-3 Alo, 4-5 Bhi, 6-7 Blo
    const int l_row = (tid + 0 * 256) >> 2;          // reused pattern below
    auto load_stage = [&](int s, int chunk) {
        char* base = smc + s * STAGEB;
        const int k0 = chunk * 32;
        (void)l_row;
#pragma unroll
        for (int g = 0; g < 2; ++g) {
            const int idx = tid + g * 256;           // 0..511
            const int row = idx >> 2, cc = idx & 3;
            const uint32_t so = (uint32_t)(row * SROWB + cc * 16);
            const size_t ga = (size_t)(bm + row) * 1024 + k0 + cc * 8;
            const size_t gb = (size_t)(bn + row) * 1024 + k0 + cc * 8;
            cpa16(smem_u32(base + so), Ahi + ga);
            cpa16(smem_u32(base + 64 + so), Alo + ga);
            cpa16(smem_u32(base + REG_B + so), Bhi + gb);
            cpa16(smem_u32(base + REG_B + 64 + so), Blo + gb);
        }
        asm volatile("cp.async.commit_group;" ::: "memory");
    };

    load_stage(0, 0);
    load_stage(1, 1);

    for (int c = 0; c < 32; ++c) {
        const int nc = c + 2;
        if (nc < 32) {
            load_stage(nc % 3, nc);
            asm volatile("cp.async.wait_group 1;" ::: "memory");
        } else {
            asm volatile("cp.async.wait_group 0;" ::: "memory");
        }
        __syncthreads();

        const uint32_t sbase = sb0 + (c % 3) * STAGEB;
#pragma unroll
        for (int ks = 0; ks < 2; ++ks) {
            uint32_t bh[2][4], bl[2][4];
#pragma unroll
            for (int np = 0; np < 2; ++np) {
                const uint32_t bb = sbase + REG_B + (wn + np * 16) * SROWB
                                    + gb_off + ks * 32;
                ldsm4(bh[np], bb);
                ldsm4(bl[np], bb + 64);
            }
#pragma unroll
            for (int mf = 0; mf < 4; ++mf) {
                uint32_t ah[4], al[4];
                const uint32_t ab = sbase + (wm + mf * 16) * SROWB
                                    + ga_off + ks * 32;
                ldsm4(ah, ab);
                ldsm4(al, ab + 64);
                // term 1: Ah*Bh  (4 independent accs)
#pragma unroll
                for (int nf = 0; nf < 4; ++nf)
                    mma_bf16(acc[mf][nf], ah, bh[nf >> 1] + (nf & 1) * 2);
                // term 2: Ah*Bl
#pragma unroll
                for (int nf = 0; nf < 4; ++nf)
                    mma_bf16(acc[mf][nf], ah, bl[nf >> 1] + (nf & 1) * 2);
                // term 3: Al*Bh
#pragma unroll
                for (int nf = 0; nf < 4; ++nf)
                    mma_bf16(acc[mf][nf], al, bh[nf >> 1] + (nf & 1) * 2);
            }
        }
        __syncthreads();
    }

    // epilogue (c0,c1 -> row lr, c2,c3 -> row lr+8; cols 2lc,2lc+1)
#pragma unroll
    for (int mf = 0; mf < 4; ++mf) {
        const int r0 = bm + wm + mf * 16 + lr;
#pragma unroll
        for (int nf = 0; nf < 4; ++nf) {
            const int col = bn + wn + nf * 8 + lc * 2;
            *(float2*)(C + (size_t)r0 * Nstride + col) =
                make_float2(acc[mf][nf][0], acc[mf][nf][1]);
            *(float2*)(C + (size_t)(r0 + 8) * Nstride + col) =
                make_float2(acc[mf][nf][2], acc[mf][nf][3]);
        }
    }
}

// ---------------------------------------------------------------------------
// Fused RMSNorm + RoPE on q and k, in place in g_qkv.
// ---------------------------------------------------------------------------
__global__ __launch_bounds__(256) void rmsrope_kernel(
    float* __restrict__ qkv,
    const float* __restrict__ rope_cos, const float* __restrict__ rope_sin,
    const float* __restrict__ qw, const float* __restrict__ kw)
{
    const int t = blockIdx.x;
    const int warp = threadIdx.x >> 5, lane = threadIdx.x & 31;
    const float c1 = rope_cos[(size_t)t * HD + lane];
    const float c2 = rope_cos[(size_t)t * HD + 32 + lane];
    const float s1 = rope_sin[(size_t)t * HD + lane];
    const float s2 = rope_sin[(size_t)t * HD + 32 + lane];

#pragma unroll
    for (int hh = 0; hh < 2; ++hh) {
        const int h = warp * 2 + hh;
#pragma unroll
        for (int qk = 0; qk < 2; ++qk) {
            float* p = qkv + (size_t)t * QKV_COLS + qk * DIM + h * HD;
            float x1 = p[lane], x2 = p[lane + 32];
            float ss = x1 * x1 + x2 * x2;
#pragma unroll
            for (int off = 16; off; off >>= 1)
                ss += __shfl_xor_sync(0xffffffffu, ss, off);
            const float r = rsqrtf(ss * (1.f / 64.f) + EPSF);
            const float* w = qk ? kw : qw;
            const float n1 = x1 * r * w[lane];
            const float n2 = x2 * r * w[lane + 32];
            p[lane]      = n1 * c1 - n2 * s1;
            p[lane + 32] = n2 * c2 + n1 * s2;
        }
    }
}

// ===========================================================================
// Flash attention, split-bf16 tensor cores (MMA terms interleaved across the
// two accumulators per np-pair to shorten dependency chains).
// ===========================================================================
#define AROWB 144
__global__ __launch_bounds__(256, 1) void attn_kernel(
    const float* __restrict__ qkv,
    __nv_bfloat16* __restrict__ ohi, __nv_bfloat16* __restrict__ olo)
{
    __shared__ __align__(128) char smb[36864];
    const uint32_t sb = smem_u32(smb);
    const int tid = threadIdx.x, wid = tid >> 5, lane = tid & 31;
    const int lr = lane >> 2, lc = lane & 3;
    const int h = blockIdx.y, b = blockIdx.z;
    const int q0 = blockIdx.x * 128;
    const int wq = wid * 16;
    const float sc = 0.125f * 1.4426950408889634f;   // D^-0.5 * log2(e)

    // --- Q: gmem fp32 -> smem bf16 hi/lo (scaled) ---
#pragma unroll
    for (int i = 0; i < 8; ++i) {
        const int slot = tid + i * 256;
        const int row = slot >> 4, c4 = (slot & 15) * 4;
        const float* src = qkv + (size_t)(b * SEQ + q0 + row) * QKV_COLS + h * HD + c4;
        float4 v = *(const float4*)src;
        v.x *= sc; v.y *= sc; v.z *= sc; v.w *= sc;
        const float h0 = bfhi(v.x), h1 = bfhi(v.y), h2 = bfhi(v.z), h3 = bfhi(v.w);
        uint32_t* dh = (uint32_t*)(smb + row * AROWB + c4 * 2);
        dh[0] = packbf(h0, h1); dh[1] = packbf(h2, h3);
        uint32_t* dl = (uint32_t*)(smb + 18432 + row * AROWB + c4 * 2);
        dl[0] = packbf(v.x - h0, v.y - h1); dl[1] = packbf(v.z - h2, v.w - h3);
    }
    __syncthreads();

    // --- Q fragments (persistent) ---
    const uint32_t a_off =
        (uint32_t)((lane & 7) + ((lane >> 3) & 1) * 8) * AROWB + ((lane >> 4) & 1) * 16;
    const uint32_t b_off =
        (uint32_t)((lane & 7) + ((lane >> 4) & 1) * 8) * AROWB + ((lane >> 3) & 1) * 16;
    const uint32_t v_off =
        (uint32_t)(lane & 15) * AROWB + ((lane >> 4) & 1) * 16;
    uint32_t qh[4][4], ql[4][4];
#pragma unroll
    for (int ks = 0; ks < 4; ++ks) {
        ldsm4(qh[ks], sb + wq * AROWB + a_off + ks * 32);
        ldsm4(ql[ks], sb + 18432 + wq * AROWB + a_off + ks * 32);
    }
    __syncthreads();   // Q smem region now free for K/V

    float m0 = -1e30f, m1 = -1e30f, l0 = 0.f, l1 = 0.f;
    float o[8][4];
#pragma unroll
    for (int nf = 0; nf < 8; ++nf)
#pragma unroll
        for (int r = 0; r < 4; ++r) o[nf][r] = 0.f;

    for (int kb = 0; kb < 16; ++kb) {
        // --- K,V: gmem fp32 -> smem bf16 hi/lo ---
#pragma unroll
        for (int i = 0; i < 4; ++i) {
            const int slot = tid + i * 256;
            const int row = slot >> 4, c4 = (slot & 15) * 4;
            const float* kp =
                qkv + (size_t)(b * SEQ + kb * 64 + row) * QKV_COLS + DIM + h * HD + c4;
            const float4 kv = *(const float4*)kp;
            const float4 vv = *(const float4*)(kp + DIM);
            const float kh0 = bfhi(kv.x), kh1 = bfhi(kv.y),
                        kh2 = bfhi(kv.z), kh3 = bfhi(kv.w);
            const float vh0 = bfhi(vv.x), vh1 = bfhi(vv.y),
                        vh2 = bfhi(vv.z), vh3 = bfhi(vv.w);
            uint32_t* d;
            d = (uint32_t*)(smb + row * AROWB + c4 * 2);            // Khi
            d[0] = packbf(kh0, kh1); d[1] = packbf(kh2, kh3);
            d = (uint32_t*)(smb + 9216 + row * AROWB + c4 * 2);     // Klo
            d[0] = packbf(kv.x - kh0, kv.y - kh1);
            d[1] = packbf(kv.z - kh2, kv.w - kh3);
            d = (uint32_t*)(smb + 18432 + row * AROWB + c4 * 2);    // Vhi
            d[0] = packbf(vh0, vh1); d[1] = packbf(vh2, vh3);
            d = (uint32_t*)(smb + 27648 + row * AROWB + c4 * 2);    // Vlo
            d[0] = packbf(vv.x - vh0, vv.y - vh1);
            d[1] = packbf(vv.z - vh2, vv.w - vh3);
        }
        __syncthreads();

        // --- S = Q K^T (3-term, accumulator-pair interleaved) ---
        float s[8][4];
#pragma unroll
        for (int nf = 0; nf < 8; ++nf)
#pragma unroll
            for (int r = 0; r < 4; ++r) s[nf][r] = 0.f;
#pragma unroll
        for (int ks = 0; ks < 4; ++ks)
#pragma unroll
            for (int np = 0; np < 4; ++np) {
                uint32_t bh[4], bl[4];
                ldsm4(bh, sb + np * 16 * AROWB + b_off + ks * 32);
                ldsm4(bl, sb + 9216 + np * 16 * AROWB + b_off + ks * 32);
                mma_bf16(s[2 * np],     qh[ks], bh);
                mma_bf16(s[2 * np + 1], qh[ks], bh + 2);
                mma_bf16(s[2 * np],     qh[ks], bl);
                mma_bf16(s[2 * np + 1], qh[ks], bl + 2);
                mma_bf16(s[2 * np],     ql[ks], bh);
                mma_bf16(s[2 * np + 1], ql[ks], bh + 2);
            }

        // --- online softmax (rows lr and lr+8; 4 lanes per row share lc) ---
        float mx0 = -1e30f, mx1 = -1e30f;
#pragma unroll
        for (int nf = 0; nf < 8; ++nf) {
            mx0 = fmaxf(mx0, fmaxf(s[nf][0], s[nf][1]));
            mx1 = fmaxf(mx1, fmaxf(s[nf][2], s[nf][3]));
        }
        mx0 = fmaxf(mx0, __shfl_xor_sync(0xffffffffu, mx0, 1));
        mx0 = fmaxf(mx0, __shfl_xor_sync(0xffffffffu, mx0, 2));
        mx1 = fmaxf(mx1, __shfl_xor_sync(0xffffffffu, mx1, 1));
        mx1 = fmaxf(mx1, __shfl_xor_sync(0xffffffffu, mx1, 2));
        const float nm0 = fmaxf(m0, mx0), nm1 = fmaxf(m1, mx1);
        const float cr0 = ex2(m0 - nm0), cr1 = ex2(m1 - nm1);
        m0 = nm0; m1 = nm1;
        float sum0 = 0.f, sum1 = 0.f;
#pragma unroll
        for (int nf = 0; nf < 8; ++nf) {
            s[nf][0] = ex2(s[nf][0] - nm0); sum0 += s[nf][0];
            s[nf][1] = ex2(s[nf][1] - nm0); sum0 += s[nf][1];
            s[nf][2] = ex2(s[nf][2] - nm1); sum1 += s[nf][2];
            s[nf][3] = ex2(s[nf][3] - nm1); sum1 += s[nf][3];
        }
        sum0 += __shfl_xor_sync(0xffffffffu, sum0, 1);
        sum0 += __shfl_xor_sync(0xffffffffu, sum0, 2);
        sum1 += __shfl_xor_sync(0xffffffffu, sum1, 1);
        sum1 += __shfl_xor_sync(0xffffffffu, sum1, 2);
        l0 = l0 * cr0 + sum0;
        l1 = l1 * cr1 + sum1;
#pragma unroll
        for (int nf = 0; nf < 8; ++nf) {
            o[nf][0] *= cr0; o[nf][1] *= cr0;
            o[nf][2] *= cr1; o[nf][3] *= cr1;
        }

        // --- pack P hi/lo into A-operand fragments ---
        uint32_t ph[4][4], pl[4][4];
#pragma unroll
        for (int ks = 0; ks < 4; ++ks) {
            const float p00 = s[2 * ks][0],     p01 = s[2 * ks][1];
            const float p10 = s[2 * ks][2],     p11 = s[2 * ks][3];
            const float p20 = s[2 * ks + 1][0], p21 = s[2 * ks + 1][1];
            const float p30 = s[2 * ks + 1][2], p31 = s[2 * ks + 1][3];
            const float h00 = bfhi(p00), h01 = bfhi(p01);
            const float h10 = bfhi(p10), h11 = bfhi(p11);
            const float h20 = bfhi(p20), h21 = bfhi(p21);
            const float h30 = bfhi(p30), h31 = bfhi(p31);
            ph[ks][0] = packbf(h00, h01); pl[ks][0] = packbf(p00 - h00, p01 - h01);
            ph[ks][1] = packbf(h10, h11); pl[ks][1] = packbf(p10 - h10, p11 - h11);
            ph[ks][2] = packbf(h20, h21); pl[ks][2] = packbf(p20 - h20, p21 - h21);
            ph[ks][3] = packbf(h30, h31); pl[ks][3] = packbf(p30 - h30, p31 - h31);
        }

        // --- O += P V (3-term, pair-interleaved), V via ldmatrix.trans ---
#pragma unroll
        for (int ks = 0; ks < 4; ++ks)
#pragma unroll
            for (int ng = 0; ng < 4; ++ng) {
                uint32_t vh[4], vl[4];
                ldsm4t(vh, sb + 18432 + ks * 2304 + v_off + ng * 32);
                ldsm4t(vl, sb + 27648 + ks * 2304 + v_off + ng * 32);
                mma_bf16(o[2 * ng],     ph[ks], vh);
                mma_bf16(o[2 * ng + 1], ph[ks], vh + 2);
                mma_bf16(o[2 * ng],     ph[ks], vl);
                mma_bf16(o[2 * ng + 1], ph[ks], vl + 2);
                mma_bf16(o[2 * ng],     pl[ks], vh);
                mma_bf16(o[2 * ng + 1], pl[ks], vh + 2);
            }
        __syncthreads();
    }

    // --- epilogue: normalize and emit split-bf16 ---
    const float i0 = 1.f / l0, i1 = 1.f / l1;
    const int t0 = b * SEQ + q0 + wq + lr;
#pragma unroll
    for (int nf = 0; nf < 8; ++nf) {
        const int col = h * HD + nf * 8 + lc * 2;
        const float v0 = o[nf][0] * i0, v1 = o[nf][1] * i0;
        const float h0 = bfhi(v0), h1 = bfhi(v1);
        ((uint32_t*)ohi)[((size_t)t0 * DIM + col) >> 1] = packbf(h0, h1);
        ((uint32_t*)olo)[((size_t)t0 * DIM + col) >> 1] = packbf(v0 - h0, v1 - h1);
        const float v2 = o[nf][2] * i1, v3 = o[nf][3] * i1;
        const float h2 = bfhi(v2), h3 = bfhi(v3);
        ((uint32_t*)ohi)[((size_t)(t0 + 8) * DIM + col) >> 1] = packbf(h2, h3);
        ((uint32_t*)olo)[((size_t)(t0 + 8) * DIM + col) >> 1] = packbf(v2 - h2, v3 - h3);
    }
}

// ---------------------------------------------------------------------------
extern "C" void kernel_launch(void* const* d_in, const int* in_sizes, int n_in,
                              void* d_out, int out_size)
{
    const float *x = 0, *rc = 0, *rs = 0, *wqkv = 0, *wproj = 0, *qw = 0, *kw = 0;
    for (int i = 0; i < n_in; ++i) {
        const int s = in_sizes[i];
        if (s == T_TOK * DIM && !x)            x = (const float*)d_in[i];
        else if (s == T_TOK * HD)              { if (!rc) rc = (const float*)d_in[i];
                                                 else if (!rs) rs = (const float*)d_in[i]; }
        else if (s == QKV_COLS * DIM)          wqkv = (const float*)d_in[i];
        else if (s == DIM * DIM && !wproj)     wproj = (const float*)d_in[i];
        else if (s == HD)                      { if (!qw) qw = (const float*)d_in[i];
                                                 else if (!kw) kw = (const float*)d_in[i]; }
    }
    float* out = (float*)d_out;

    void *pqkv, *pxh, *pxl, *pwqh, *pwql, *pwph, *pwpl, *pah, *pal;
    cudaGetSymbolAddress(&pqkv, g_qkv);
    cudaGetSymbolAddress(&pxh, g_xhi);  cudaGetSymbolAddress(&pxl, g_xlo);
    cudaGetSymbolAddress(&pwqh, g_wqhi); cudaGetSymbolAddress(&pwql, g_wqlo);
    cudaGetSymbolAddress(&pwph, g_wphi); cudaGetSymbolAddress(&pwpl, g_wplo);
    cudaGetSymbolAddress(&pah, g_ahi);  cudaGetSymbolAddress(&pal, g_alo);

    cudaFuncSetAttribute(gemm_split_kernel,
                         cudaFuncAttributeMaxDynamicSharedMemorySize, GSMEM);

    // 0) fp32 -> (hi,lo) bf16 splits
    split_kernel<<<(T_TOK * DIM / 4 + 255) / 256, 256>>>(
        x, (__nv_bfloat16*)pxh, (__nv_bfloat16*)pxl, T_TOK * DIM / 4);
    split_kernel<<<(QKV_COLS * DIM / 4 + 255) / 256, 256>>>(
        wqkv, (__nv_bfloat16*)pwqh, (__nv_bfloat16*)pwql, QKV_COLS * DIM / 4);
    split_kernel<<<(DIM * DIM / 4 + 255) / 256, 256>>>(
        wproj, (__nv_bfloat16*)pwph, (__nv_bfloat16*)pwpl, DIM * DIM / 4);

    // 1) QKV = x @ w_qkv^T
    gemm_split_kernel<<<dim3(QKV_COLS / 128, T_TOK / 128), 256, GSMEM>>>(
        (__nv_bfloat16*)pxh, (__nv_bfloat16*)pxl,
        (__nv_bfloat16*)pwqh, (__nv_bfloat16*)pwql, (float*)pqkv, QKV_COLS);
    // 2) RMSNorm + RoPE on q,k (in place)
    rmsrope_kernel<<<T_TOK, 256>>>((float*)pqkv, rc, rs, qw, kw);
    // 3) Attention (split-bf16 tensor cores; emits split-bf16 output)
    attn_kernel<<<dim3(SEQ / 128, HEADS, BATCH), 256>>>(
        (float*)pqkv, (__nv_bfloat16*)pah, (__nv_bfloat16*)pal);
    // 4) out = attn @ w_proj^T
    gemm_split_kernel<<<dim3(DIM / 128, T_TOK / 128), 256, GSMEM>>>(
        (__nv_bfloat16*)pah, (__nv_bfloat16*)pal,
        (__nv_bfloat16*)pwph, (__nv_bfloat16*)pwpl, out, DIM);
}

// round 7
// speedup vs baseline: 2.6799x; 1.0663x over previous
#include <cuda_runtime.h>
#include <cuda_bf16.h>
#include <math.h>
#include <stdint.h>

// Problem constants (fixed by reference setup_inputs)
#define T_TOK   8192
#define DIM     1024
#define HEADS   16
#define HD      64
#define SEQ     1024
#define BATCH   8
#define QKV_COLS 3072
#define EPSF 1.1920928955078125e-07f

// Scratch (device globals — no allocation allowed)
__device__ float g_qkv[(size_t)T_TOK * QKV_COLS];               // [T,3,H,D] fp32
__device__ __nv_bfloat16 g_xhi[(size_t)T_TOK * DIM];
__device__ __nv_bfloat16 g_xlo[(size_t)T_TOK * DIM];
__device__ __nv_bfloat16 g_wqhi[(size_t)QKV_COLS * DIM];
__device__ __nv_bfloat16 g_wqlo[(size_t)QKV_COLS * DIM];
__device__ __nv_bfloat16 g_wphi[(size_t)DIM * DIM];
__device__ __nv_bfloat16 g_wplo[(size_t)DIM * DIM];
__device__ __nv_bfloat16 g_ahi[(size_t)T_TOK * DIM];
__device__ __nv_bfloat16 g_alo[(size_t)T_TOK * DIM];
// head-major [B,H,S,D] split q/k/v
#define HSZ ((size_t)BATCH * HEADS * SEQ * HD)
__device__ __nv_bfloat16 g_qh[HSZ], g_ql[HSZ];
__device__ __nv_bfloat16 g_kh[HSZ], g_kl[HSZ];
__device__ __nv_bfloat16 g_vh[HSZ], g_vl[HSZ];

// ===========================================================================
// Common helpers
// ===========================================================================
__device__ __forceinline__ uint32_t smem_u32(const void* p) {
    uint32_t a;
    asm("{ .reg .u64 t; cvta.to.shared.u64 t, %1; cvt.u32.u64 %0, t; }"
        : "=r"(a) : "l"(p));
    return a;
}
__device__ __forceinline__ void cpa16(uint32_t s, const void* g) {
    asm volatile("cp.async.cg.shared.global [%0], [%1], 16;" :: "r"(s), "l"(g));
}
__device__ __forceinline__ void mma_bf16(float* d, const uint32_t* a,
                                         const uint32_t* b) {
    asm volatile(
        "mma.sync.aligned.m16n8k16.row.col.f32.bf16.bf16.f32 "
        "{%0,%1,%2,%3}, {%4,%5,%6,%7}, {%8,%9}, {%0,%1,%2,%3};"
        : "+f"(d[0]), "+f"(d[1]), "+f"(d[2]), "+f"(d[3])
        : "r"(a[0]), "r"(a[1]), "r"(a[2]), "r"(a[3]), "r"(b[0]), "r"(b[1]));
}
__device__ __forceinline__ void ldsm4(uint32_t* r, uint32_t a) {
    asm volatile("ldmatrix.sync.aligned.m8n8.x4.shared.b16 {%0,%1,%2,%3}, [%4];"
        : "=r"(r[0]), "=r"(r[1]), "=r"(r[2]), "=r"(r[3]) : "r"(a));
}
__device__ __forceinline__ void ldsm4t(uint32_t* r, uint32_t a) {
    asm volatile("ldmatrix.sync.aligned.m8n8.x4.trans.shared.b16 {%0,%1,%2,%3}, [%4];"
        : "=r"(r[0]), "=r"(r[1]), "=r"(r[2]), "=r"(r[3]) : "r"(a));
}
__device__ __forceinline__ float ex2(float x) {
    float r; asm("ex2.approx.f32 %0, %1;" : "=f"(r) : "f"(x)); return r;
}
__device__ __forceinline__ uint32_t packbf(float lo, float hi) {
    uint32_t r;
    asm("cvt.rn.bf16x2.f32 %0, %1, %2;" : "=r"(r) : "f"(hi), "f"(lo));
    return r;
}
__device__ __forceinline__ float bfhi(float x) {
    return __bfloat162float(__float2bfloat16_rn(x));
}

// ===========================================================================
// fp32 -> (hi, lo) bf16 split
// ===========================================================================
__global__ __launch_bounds__(256) void split_kernel(
    const float* __restrict__ src, __nv_bfloat16* __restrict__ hi,
    __nv_bfloat16* __restrict__ lo, int n4)
{
    const int i = blockIdx.x * 256 + threadIdx.x;
    if (i >= n4) return;
    const float4 v = ((const float4*)src)[i];
    float h0 = bfhi(v.x), h1 = bfhi(v.y), h2 = bfhi(v.z), h3 = bfhi(v.w);
    uint32_t* hp = (uint32_t*)(hi) + i * 2;
    hp[0] = packbf(h0, h1);
    hp[1] = packbf(h2, h3);
    uint32_t* lp = (uint32_t*)(lo) + i * 2;
    lp[0] = packbf(v.x - h0, v.y - h1);
    lp[1] = packbf(v.z - h2, v.w - h3);
}

// ===========================================================================
// Split-bf16 GEMM, 2 CTAs/SM (unchanged from R6).
// ===========================================================================
#define SROWB 144
#define REG_B 18432
#define STAGEB 36864
#define GSMEM (3 * STAGEB)

__global__ __launch_bounds__(256, 2) void gemm_split_kernel(
    const __nv_bfloat16* __restrict__ Ahi, const __nv_bfloat16* __restrict__ Alo,
    const __nv_bfloat16* __restrict__ Bhi, const __nv_bfloat16* __restrict__ Blo,
    float* __restrict__ C, int Nstride)
{
    extern __shared__ char smc[];
    const int tid = threadIdx.x, wid = tid >> 5, lane = tid & 31;
    const int bm = blockIdx.y * 128, bn = blockIdx.x * 128;
    const int wm = (wid >> 2) * 64;
    const int wn = (wid & 3) * 32;
    const int lr = lane >> 2, lc = lane & 3;
    const uint32_t sb0 = smem_u32(smc);
    const uint32_t ga_off =
        (uint32_t)((lane & 7) + ((lane >> 3) & 1) * 8) * SROWB +
        ((lane >> 4) & 1) * 16;
    const uint32_t gb_off =
        (uint32_t)((lane & 7) + ((lane >> 4) & 1) * 8) * SROWB +
        ((lane >> 3) & 1) * 16;

    float acc[4][4][4];
#pragma unroll
    for (int i = 0; i < 4; ++i)
#pragma unroll
        for (int j = 0; j < 4; ++j)
#pragma unroll
            for (int r = 0; r < 4; ++r) acc[i][j][r] = 0.f;

    auto load_stage = [&](int s, int chunk) {
        char* base = smc + s * STAGEB;
        const int k0 = chunk * 32;
#pragma unroll
        for (int g = 0; g < 2; ++g) {
            const int idx = tid + g * 256;
            const int row = idx >> 2, cc = idx & 3;
            const uint32_t so = (uint32_t)(row * SROWB + cc * 16);
            const size_t ga = (size_t)(bm + row) * 1024 + k0 + cc * 8;
            const size_t gb = (size_t)(bn + row) * 1024 + k0 + cc * 8;
            cpa16(smem_u32(base + so), Ahi + ga);
            cpa16(smem_u32(base + 64 + so), Alo + ga);
            cpa16(smem_u32(base + REG_B + so), Bhi + gb);
            cpa16(smem_u32(base + REG_B + 64 + so), Blo + gb);
        }
        asm volatile("cp.async.commit_group;" ::: "memory");
    };

    load_stage(0, 0);
    load_stage(1, 1);

    for (int c = 0; c < 32; ++c) {
        const int nc = c + 2;
        if (nc < 32) {
            load_stage(nc % 3, nc);
            asm volatile("cp.async.wait_group 1;" ::: "memory");
        } else {
            asm volatile("cp.async.wait_group 0;" ::: "memory");
        }
        __syncthreads();

        const uint32_t sbase = sb0 + (c % 3) * STAGEB;
#pragma unroll
        for (int ks = 0; ks < 2; ++ks) {
            uint32_t bh[2][4], bl[2][4];
#pragma unroll
            for (int np = 0; np < 2; ++np) {
                const uint32_t bb = sbase + REG_B + (wn + np * 16) * SROWB
                                    + gb_off + ks * 32;
                ldsm4(bh[np], bb);
                ldsm4(bl[np], bb + 64);
            }
#pragma unroll
            for (int mf = 0; mf < 4; ++mf) {
                uint32_t ah[4], al[4];
                const uint32_t ab = sbase + (wm + mf * 16) * SROWB
                                    + ga_off + ks * 32;
                ldsm4(ah, ab);
                ldsm4(al, ab + 64);
#pragma unroll
                for (int nf = 0; nf < 4; ++nf)
                    mma_bf16(acc[mf][nf], ah, bh[nf >> 1] + (nf & 1) * 2);
#pragma unroll
                for (int nf = 0; nf < 4; ++nf)
                    mma_bf16(acc[mf][nf], ah, bl[nf >> 1] + (nf & 1) * 2);
#pragma unroll
                for (int nf = 0; nf < 4; ++nf)
                    mma_bf16(acc[mf][nf], al, bh[nf >> 1] + (nf & 1) * 2);
            }
        }
        __syncthreads();
    }

#pragma unroll
    for (int mf = 0; mf < 4; ++mf) {
        const int r0 = bm + wm + mf * 16 + lr;
#pragma unroll
        for (int nf = 0; nf < 4; ++nf) {
            const int col = bn + wn + nf * 8 + lc * 2;
            *(float2*)(C + (size_t)r0 * Nstride + col) =
                make_float2(acc[mf][nf][0], acc[mf][nf][1]);
            *(float2*)(C + (size_t)(r0 + 8) * Nstride + col) =
                make_float2(acc[mf][nf][2], acc[mf][nf][3]);
        }
    }
}

// ---------------------------------------------------------------------------
// Fused RMSNorm + RoPE on q,k + split of q,k,v to bf16 hi/lo in head-major
// [B,H,S,D] layout. q is pre-scaled by D^-0.5 * log2(e) for the attention.
// ---------------------------------------------------------------------------
__global__ __launch_bounds__(256) void rmsrope_kernel(
    const float* __restrict__ qkv,
    const float* __restrict__ rope_cos, const float* __restrict__ rope_sin,
    const float* __restrict__ qw, const float* __restrict__ kw,
    __nv_bfloat16* __restrict__ qh, __nv_bfloat16* __restrict__ ql,
    __nv_bfloat16* __restrict__ kh, __nv_bfloat16* __restrict__ kl,
    __nv_bfloat16* __restrict__ vh, __nv_bfloat16* __restrict__ vl)
{
    const int t = blockIdx.x;
    const int warp = threadIdx.x >> 5, lane = threadIdx.x & 31;
    const int bb = t >> 10, ss = t & 1023;
    const float c1 = rope_cos[(size_t)t * HD + lane];
    const float c2 = rope_cos[(size_t)t * HD + 32 + lane];
    const float s1 = rope_sin[(size_t)t * HD + lane];
    const float s2 = rope_sin[(size_t)t * HD + 32 + lane];
    const float qscale = 0.125f * 1.4426950408889634f;

#pragma unroll
    for (int hh = 0; hh < 2; ++hh) {
        const int h = warp * 2 + hh;
        const size_t dst = ((size_t)(bb * HEADS + h) * SEQ + ss) * HD;
#pragma unroll
        for (int qk = 0; qk < 2; ++qk) {
            const float* p = qkv + (size_t)t * QKV_COLS + qk * DIM + h * HD;
            float x1 = p[lane], x2 = p[lane + 32];
            float sq = x1 * x1 + x2 * x2;
#pragma unroll
            for (int off = 16; off; off >>= 1)
                sq += __shfl_xor_sync(0xffffffffu, sq, off);
            const float r = rsqrtf(sq * (1.f / 64.f) + EPSF);
            const float* w = qk ? kw : qw;
            const float n1 = x1 * r * w[lane];
            const float n2 = x2 * r * w[lane + 32];
            float r1 = n1 * c1 - n2 * s1;
            float r2 = n2 * c2 + n1 * s2;
            if (qk == 0) { r1 *= qscale; r2 *= qscale; }
            __nv_bfloat16* dh = qk ? kh : qh;
            __nv_bfloat16* dl = qk ? kl : ql;
            const float h1 = bfhi(r1), h2v = bfhi(r2);
            dh[dst + lane] = __float2bfloat16_rn(h1);
            dh[dst + lane + 32] = __float2bfloat16_rn(h2v);
            dl[dst + lane] = __float2bfloat16_rn(r1 - h1);
            dl[dst + lane + 32] = __float2bfloat16_rn(r2 - h2v);
        }
        // v: plain split
        const float* pv = qkv + (size_t)t * QKV_COLS + 2 * DIM + h * HD;
        const float v1 = pv[lane], v2 = pv[lane + 32];
        const float h1 = bfhi(v1), h2v = bfhi(v2);
        vh[dst + lane] = __float2bfloat16_rn(h1);
        vh[dst + lane + 32] = __float2bfloat16_rn(h2v);
        vl[dst + lane] = __float2bfloat16_rn(v1 - h1);
        vl[dst + lane + 32] = __float2bfloat16_rn(v2 - h2v);
    }
}

// ===========================================================================
// Flash attention, split-bf16 tensor cores, cp.async double-buffered K/V.
// Rows pack hi|lo: 128B hi + 128B lo + 16B pad = 272B.
// smem: stage s in {0,1}: K at s*34816, V at s*34816+17408. Q phase reuses
// stage 0+1 region (128 rows x 272 = 34816 bytes).
// ===========================================================================
#define KROWB 272
#define KTILE 17408                      // 64 * 272
#define KSTG  34816                      // K + V
#define ATT_SMEM (2 * KSTG)              // 69632

__global__ __launch_bounds__(256, 1) void attn_kernel(
    const __nv_bfloat16* __restrict__ qh, const __nv_bfloat16* __restrict__ ql,
    const __nv_bfloat16* __restrict__ kh, const __nv_bfloat16* __restrict__ kl,
    const __nv_bfloat16* __restrict__ vh, const __nv_bfloat16* __restrict__ vl,
    __nv_bfloat16* __restrict__ ohi, __nv_bfloat16* __restrict__ olo)
{
    extern __shared__ char sma[];
    const uint32_t sb = smem_u32(sma);
    const int tid = threadIdx.x, wid = tid >> 5, lane = tid & 31;
    const int lr = lane >> 2, lc = lane & 3;
    const int h = blockIdx.y, b = blockIdx.z;
    const int q0 = blockIdx.x * 128;
    const int wq = wid * 16;
    const size_t hb = (size_t)(b * HEADS + h) * SEQ * HD;   // head base

    // --- Q tile load (cp.async, no conversion) ---
#pragma unroll
    for (int i = 0; i < 8; ++i) {
        const int slot = tid + i * 256;
        const int row = slot >> 4, c = slot & 15;
        const __nv_bfloat16* src = (c < 8 ? qh : ql) + hb + (size_t)(q0 + row) * HD + (c & 7) * 8;
        cpa16(sb + row * KROWB + c * 16, src);
    }
    asm volatile("cp.async.commit_group;" ::: "memory");
    asm volatile("cp.async.wait_group 0;" ::: "memory");
    __syncthreads();

    // --- Q fragments (persistent) ---
    const uint32_t a_off =
        (uint32_t)((lane & 7) + ((lane >> 3) & 1) * 8) * KROWB + ((lane >> 4) & 1) * 16;
    const uint32_t b_off =
        (uint32_t)((lane & 7) + ((lane >> 4) & 1) * 8) * KROWB + ((lane >> 3) & 1) * 16;
    const uint32_t v_off =
        (uint32_t)(lane & 15) * KROWB + ((lane >> 4) & 1) * 16;
    uint32_t qfh[4][4], qfl[4][4];
#pragma unroll
    for (int ks = 0; ks < 4; ++ks) {
        ldsm4(qfh[ks], sb + wq * KROWB + a_off + ks * 32);
        ldsm4(qfl[ks], sb + wq * KROWB + a_off + ks * 32 + 128);
    }
    __syncthreads();   // Q region free for K/V stages

    auto load_kv = [&](int kb, int s) {
        const uint32_t kst = sb + s * KSTG;
#pragma unroll
        for (int i = 0; i < 4; ++i) {
            const int slot = tid + i * 256;
            const int row = slot >> 4, c = slot & 15;
            const size_t g = hb + (size_t)(kb * 64 + row) * HD + (c & 7) * 8;
            cpa16(kst + row * KROWB + c * 16, (c < 8 ? kh : kl) + g);
        }
#pragma unroll
        for (int i = 0; i < 4; ++i) {
            const int slot = tid + i * 256;
            const int row = slot >> 4, c = slot & 15;
            const size_t g = hb + (size_t)(kb * 64 + row) * HD + (c & 7) * 8;
            cpa16(kst + KTILE + row * KROWB + c * 16, (c < 8 ? vh : vl) + g);
        }
        asm volatile("cp.async.commit_group;" ::: "memory");
    };

    load_kv(0, 0);
    load_kv(1, 1);

    float m0 = -1e30f, m1 = -1e30f, l0 = 0.f, l1 = 0.f;
    float o[8][4];
#pragma unroll
    for (int nf = 0; nf < 8; ++nf)
#pragma unroll
        for (int r = 0; r < 4; ++r) o[nf][r] = 0.f;

    for (int kb = 0; kb < 16; ++kb) {
        const int st = kb & 1;
        const uint32_t kbase = sb + st * KSTG;
        const uint32_t vbase = kbase + KTILE;
        if (kb < 15) { asm volatile("cp.async.wait_group 1;" ::: "memory"); }
        else         { asm volatile("cp.async.wait_group 0;" ::: "memory"); }
        __syncthreads();

        // --- S = Q K^T (3-term, pair-interleaved) ---
        float s[8][4];
#pragma unroll
        for (int nf = 0; nf < 8; ++nf)
#pragma unroll
            for (int r = 0; r < 4; ++r) s[nf][r] = 0.f;
#pragma unroll
        for (int ks = 0; ks < 4; ++ks)
#pragma unroll
            for (int np = 0; np < 4; ++np) {
                uint32_t bh[4], bl[4];
                const uint32_t ba = kbase + np * 16 * KROWB + b_off + ks * 32;
                ldsm4(bh, ba);
                ldsm4(bl, ba + 128);
                mma_bf16(s[2 * np],     qfh[ks], bh);
                mma_bf16(s[2 * np + 1], qfh[ks], bh + 2);
                mma_bf16(s[2 * np],     qfh[ks], bl);
                mma_bf16(s[2 * np + 1], qfh[ks], bl + 2);
                mma_bf16(s[2 * np],     qfl[ks], bh);
                mma_bf16(s[2 * np + 1], qfl[ks], bh + 2);
            }

        // --- online softmax ---
        float mx0 = -1e30f, mx1 = -1e30f;
#pragma unroll
        for (int nf = 0; nf < 8; ++nf) {
            mx0 = fmaxf(mx0, fmaxf(s[nf][0], s[nf][1]));
            mx1 = fmaxf(mx1, fmaxf(s[nf][2], s[nf][3]));
        }
        mx0 = fmaxf(mx0, __shfl_xor_sync(0xffffffffu, mx0, 1));
        mx0 = fmaxf(mx0, __shfl_xor_sync(0xffffffffu, mx0, 2));
        mx1 = fmaxf(mx1, __shfl_xor_sync(0xffffffffu, mx1, 1));
        mx1 = fmaxf(mx1, __shfl_xor_sync(0xffffffffu, mx1, 2));
        const float nm0 = fmaxf(m0, mx0), nm1 = fmaxf(m1, mx1);
        const float cr0 = ex2(m0 - nm0), cr1 = ex2(m1 - nm1);
        m0 = nm0; m1 = nm1;
        float sum0 = 0.f, sum1 = 0.f;
#pragma unroll
        for (int nf = 0; nf < 8; ++nf) {
            s[nf][0] = ex2(s[nf][0] - nm0); sum0 += s[nf][0];
            s[nf][1] = ex2(s[nf][1] - nm0); sum0 += s[nf][1];
            s[nf][2] = ex2(s[nf][2] - nm1); sum1 += s[nf][2];
            s[nf][3] = ex2(s[nf][3] - nm1); sum1 += s[nf][3];
        }
        sum0 += __shfl_xor_sync(0xffffffffu, sum0, 1);
        sum0 += __shfl_xor_sync(0xffffffffu, sum0, 2);
        sum1 += __shfl_xor_sync(0xffffffffu, sum1, 1);
        sum1 += __shfl_xor_sync(0xffffffffu, sum1, 2);
        l0 = l0 * cr0 + sum0;
        l1 = l1 * cr1 + sum1;
#pragma unroll
        for (int nf = 0; nf < 8; ++nf) {
            o[nf][0] *= cr0; o[nf][1] *= cr0;
            o[nf][2] *= cr1; o[nf][3] *= cr1;
        }

        // --- pack P hi/lo into A-operand fragments ---
        uint32_t ph[4][4], pl[4][4];
#pragma unroll
        for (int ks = 0; ks < 4; ++ks) {
            const float p00 = s[2 * ks][0],     p01 = s[2 * ks][1];
            const float p10 = s[2 * ks][2],     p11 = s[2 * ks][3];
            const float p20 = s[2 * ks + 1][0], p21 = s[2 * ks + 1][1];
            const float p30 = s[2 * ks + 1][2], p31 = s[2 * ks + 1][3];
            const float h00 = bfhi(p00), h01 = bfhi(p01);
            const float h10 = bfhi(p10), h11 = bfhi(p11);
            const float h20 = bfhi(p20), h21 = bfhi(p21);
            const float h30 = bfhi(p30), h31 = bfhi(p31);
            ph[ks][0] = packbf(h00, h01); pl[ks][0] = packbf(p00 - h00, p01 - h01);
            ph[ks][1] = packbf(h10, h11); pl[ks][1] = packbf(p10 - h10, p11 - h11);
            ph[ks][2] = packbf(h20, h21); pl[ks][2] = packbf(p20 - h20, p21 - h21);
            ph[ks][3] = packbf(h30, h31); pl[ks][3] = packbf(p30 - h30, p31 - h31);
        }

        // --- O += P V (3-term, pair-interleaved) ---
#pragma unroll
        for (int ks = 0; ks < 4; ++ks)
#pragma unroll
            for (int ng = 0; ng < 4; ++ng) {
                uint32_t vfh[4], vfl[4];
                const uint32_t va = vbase + ks * 16 * KROWB + v_off + ng * 32;
                ldsm4t(vfh, va);
                ldsm4t(vfl, va + 128);
                mma_bf16(o[2 * ng],     ph[ks], vfh);
                mma_bf16(o[2 * ng + 1], ph[ks], vfh + 2);
                mma_bf16(o[2 * ng],     ph[ks], vfl);
                mma_bf16(o[2 * ng + 1], ph[ks], vfl + 2);
                mma_bf16(o[2 * ng],     pl[ks], vfh);
                mma_bf16(o[2 * ng + 1], pl[ks], vfh + 2);
            }
        __syncthreads();
        if (kb + 2 < 16) load_kv(kb + 2, st);
    }

    // --- epilogue: normalize and emit split-bf16 ---
    const float i0 = 1.f / l0, i1 = 1.f / l1;
    const int t0 = b * SEQ + q0 + wq + lr;
#pragma unroll
    for (int nf = 0; nf < 8; ++nf) {
        const int col = h * HD + nf * 8 + lc * 2;
        const float v0 = o[nf][0] * i0, v1 = o[nf][1] * i0;
        const float h0 = bfhi(v0), h1 = bfhi(v1);
        ((uint32_t*)ohi)[((size_t)t0 * DIM + col) >> 1] = packbf(h0, h1);
        ((uint32_t*)olo)[((size_t)t0 * DIM + col) >> 1] = packbf(v0 - h0, v1 - h1);
        const float v2 = o[nf][2] * i1, v3 = o[nf][3] * i1;
        const float h2 = bfhi(v2), h3 = bfhi(v3);
        ((uint32_t*)ohi)[((size_t)(t0 + 8) * DIM + col) >> 1] = packbf(h2, h3);
        ((uint32_t*)olo)[((size_t)(t0 + 8) * DIM + col) >> 1] = packbf(v2 - h2, v3 - h3);
    }
}

// ---------------------------------------------------------------------------
extern "C" void kernel_launch(void* const* d_in, const int* in_sizes, int n_in,
                              void* d_out, int out_size)
{
    const float *x = 0, *rc = 0, *rs = 0, *wqkv = 0, *wproj = 0, *qw = 0, *kw = 0;
    for (int i = 0; i < n_in; ++i) {
        const int s = in_sizes[i];
        if (s == T_TOK * DIM && !x)            x = (const float*)d_in[i];
        else if (s == T_TOK * HD)              { if (!rc) rc = (const float*)d_in[i];
                                                 else if (!rs) rs = (const float*)d_in[i]; }
        else if (s == QKV_COLS * DIM)          wqkv = (const float*)d_in[i];
        else if (s == DIM * DIM && !wproj)     wproj = (const float*)d_in[i];
        else if (s == HD)                      { if (!qw) qw = (const float*)d_in[i];
                                                 else if (!kw) kw = (const float*)d_in[i]; }
    }
    float* out = (float*)d_out;

    void *pqkv, *pxh, *pxl, *pwqh, *pwql, *pwph, *pwpl, *pah, *pal;
    void *pqh, *pql, *pkh, *pkl, *pvh, *pvl;
    cudaGetSymbolAddress(&pqkv, g_qkv);
    cudaGetSymbolAddress(&pxh, g_xhi);  cudaGetSymbolAddress(&pxl, g_xlo);
    cudaGetSymbolAddress(&pwqh, g_wqhi); cudaGetSymbolAddress(&pwql, g_wqlo);
    cudaGetSymbolAddress(&pwph, g_wphi); cudaGetSymbolAddress(&pwpl, g_wplo);
    cudaGetSymbolAddress(&pah, g_ahi);  cudaGetSymbolAddress(&pal, g_alo);
    cudaGetSymbolAddress(&pqh, g_qh);   cudaGetSymbolAddress(&pql, g_ql);
    cudaGetSymbolAddress(&pkh, g_kh);   cudaGetSymbolAddress(&pkl, g_kl);
    cudaGetSymbolAddress(&pvh, g_vh);   cudaGetSymbolAddress(&pvl, g_vl);

    cudaFuncSetAttribute(gemm_split_kernel,
                         cudaFuncAttributeMaxDynamicSharedMemorySize, GSMEM);
    cudaFuncSetAttribute(attn_kernel,
                         cudaFuncAttributeMaxDynamicSharedMemorySize, ATT_SMEM);

    // 0) fp32 -> (hi,lo) bf16 splits
    split_kernel<<<(T_TOK * DIM / 4 + 255) / 256, 256>>>(
        x, (__nv_bfloat16*)pxh, (__nv_bfloat16*)pxl, T_TOK * DIM / 4);
    split_kernel<<<(QKV_COLS * DIM / 4 + 255) / 256, 256>>>(
        wqkv, (__nv_bfloat16*)pwqh, (__nv_bfloat16*)pwql, QKV_COLS * DIM / 4);
    split_kernel<<<(DIM * DIM / 4 + 255) / 256, 256>>>(
        wproj, (__nv_bfloat16*)pwph, (__nv_bfloat16*)pwpl, DIM * DIM / 4);

    // 1) QKV = x @ w_qkv^T
    gemm_split_kernel<<<dim3(QKV_COLS / 128, T_TOK / 128), 256, GSMEM>>>(
        (__nv_bfloat16*)pxh, (__nv_bfloat16*)pxl,
        (__nv_bfloat16*)pwqh, (__nv_bfloat16*)pwql, (float*)pqkv, QKV_COLS);
    // 2) RMSNorm + RoPE + split q,k,v to head-major bf16
    rmsrope_kernel<<<T_TOK, 256>>>(
        (const float*)pqkv, rc, rs, qw, kw,
        (__nv_bfloat16*)pqh, (__nv_bfloat16*)pql,
        (__nv_bfloat16*)pkh, (__nv_bfloat16*)pkl,
        (__nv_bfloat16*)pvh, (__nv_bfloat16*)pvl);
    // 3) Attention (pure tensor-core, double-buffered)
    attn_kernel<<<dim3(SEQ / 128, HEADS, BATCH), 256, ATT_SMEM>>>(
        (__nv_bfloat16*)pqh, (__nv_bfloat16*)pql,
        (__nv_bfloat16*)pkh, (__nv_bfloat16*)pkl,
        (__nv_bfloat16*)pvh, (__nv_bfloat16*)pvl,
        (__nv_bfloat16*)pah, (__nv_bfloat16*)pal);
    // 4) out = attn @ w_proj^T
    gemm_split_kernel<<<dim3(DIM / 128, T_TOK / 128), 256, GSMEM>>>(
        (__nv_bfloat16*)pah, (__nv_bfloat16*)pal,
        (__nv_bfloat16*)pwph, (__nv_bfloat16*)pwpl, out, DIM);
}

// round 8
// speedup vs baseline: 2.6850x; 1.0019x over previous
#include <cuda_runtime.h>
#include <cuda_bf16.h>
#include <math.h>
#include <stdint.h>

// Problem constants (fixed by reference setup_inputs)
#define T_TOK   8192
#define DIM     1024
#define HEADS   16
#define HD      64
#define SEQ     1024
#define BATCH   8
#define QKV_COLS 3072
#define EPSF 1.1920928955078125e-07f

// Scratch (device globals — no allocation allowed)
__device__ float g_qkv[(size_t)T_TOK * QKV_COLS];               // [T,3,H,D] fp32
__device__ __nv_bfloat16 g_xhi[(size_t)T_TOK * DIM];
__device__ __nv_bfloat16 g_xlo[(size_t)T_TOK * DIM];
__device__ __nv_bfloat16 g_wqhi[(size_t)QKV_COLS * DIM];
__device__ __nv_bfloat16 g_wqlo[(size_t)QKV_COLS * DIM];
__device__ __nv_bfloat16 g_wphi[(size_t)DIM * DIM];
__device__ __nv_bfloat16 g_wplo[(size_t)DIM * DIM];
__device__ __nv_bfloat16 g_ahi[(size_t)T_TOK * DIM];
__device__ __nv_bfloat16 g_alo[(size_t)T_TOK * DIM];
// head-major [B,H,S,D] split q/k/v
#define HSZ ((size_t)BATCH * HEADS * SEQ * HD)
__device__ __nv_bfloat16 g_qh[HSZ], g_ql[HSZ];
__device__ __nv_bfloat16 g_kh[HSZ], g_kl[HSZ];
__device__ __nv_bfloat16 g_vh[HSZ], g_vl[HSZ];

// ===========================================================================
// Common helpers
// ===========================================================================
__device__ __forceinline__ uint32_t smem_u32(const void* p) {
    uint32_t a;
    asm("{ .reg .u64 t; cvta.to.shared.u64 t, %1; cvt.u32.u64 %0, t; }"
        : "=r"(a) : "l"(p));
    return a;
}
__device__ __forceinline__ void cpa16(uint32_t s, const void* g) {
    asm volatile("cp.async.cg.shared.global [%0], [%1], 16;" :: "r"(s), "l"(g));
}
__device__ __forceinline__ void mma_bf16(float* d, const uint32_t* a,
                                         const uint32_t* b) {
    asm volatile(
        "mma.sync.aligned.m16n8k16.row.col.f32.bf16.bf16.f32 "
        "{%0,%1,%2,%3}, {%4,%5,%6,%7}, {%8,%9}, {%0,%1,%2,%3};"
        : "+f"(d[0]), "+f"(d[1]), "+f"(d[2]), "+f"(d[3])
        : "r"(a[0]), "r"(a[1]), "r"(a[2]), "r"(a[3]), "r"(b[0]), "r"(b[1]));
}
__device__ __forceinline__ void ldsm4(uint32_t* r, uint32_t a) {
    asm volatile("ldmatrix.sync.aligned.m8n8.x4.shared.b16 {%0,%1,%2,%3}, [%4];"
        : "=r"(r[0]), "=r"(r[1]), "=r"(r[2]), "=r"(r[3]) : "r"(a));
}
__device__ __forceinline__ void ldsm4t(uint32_t* r, uint32_t a) {
    asm volatile("ldmatrix.sync.aligned.m8n8.x4.trans.shared.b16 {%0,%1,%2,%3}, [%4];"
        : "=r"(r[0]), "=r"(r[1]), "=r"(r[2]), "=r"(r[3]) : "r"(a));
}
__device__ __forceinline__ float ex2(float x) {
    float r; asm("ex2.approx.f32 %0, %1;" : "=f"(r) : "f"(x)); return r;
}
__device__ __forceinline__ uint32_t packbf(float lo, float hi) {
    uint32_t r;
    asm("cvt.rn.bf16x2.f32 %0, %1, %2;" : "=r"(r) : "f"(hi), "f"(lo));
    return r;
}
__device__ __forceinline__ float bfhi(float x) {
    return __bfloat162float(__float2bfloat16_rn(x));
}

// ===========================================================================
// fp32 -> (hi, lo) bf16 split
// ===========================================================================
__global__ __launch_bounds__(256) void split_kernel(
    const float* __restrict__ src, __nv_bfloat16* __restrict__ hi,
    __nv_bfloat16* __restrict__ lo, int n4)
{
    const int i = blockIdx.x * 256 + threadIdx.x;
    if (i >= n4) return;
    const float4 v = ((const float4*)src)[i];
    float h0 = bfhi(v.x), h1 = bfhi(v.y), h2 = bfhi(v.z), h3 = bfhi(v.w);
    uint32_t* hp = (uint32_t*)(hi) + i * 2;
    hp[0] = packbf(h0, h1);
    hp[1] = packbf(h2, h3);
    uint32_t* lp = (uint32_t*)(lo) + i * 2;
    lp[0] = packbf(v.x - h0, v.y - h1);
    lp[1] = packbf(v.z - h2, v.w - h3);
}

// ===========================================================================
// Split-bf16 GEMM, 2 CTAs/SM, A-fragment software pipelining.
// ===========================================================================
#define SROWB 144
#define REG_B 18432
#define STAGEB 36864
#define GSMEM (3 * STAGEB)

__global__ __launch_bounds__(256, 2) void gemm_split_kernel(
    const __nv_bfloat16* __restrict__ Ahi, const __nv_bfloat16* __restrict__ Alo,
    const __nv_bfloat16* __restrict__ Bhi, const __nv_bfloat16* __restrict__ Blo,
    float* __restrict__ C, int Nstride)
{
    extern __shared__ char smc[];
    const int tid = threadIdx.x, wid = tid >> 5, lane = tid & 31;
    const int bm = blockIdx.y * 128, bn = blockIdx.x * 128;
    const int wm = (wid >> 2) * 64;
    const int wn = (wid & 3) * 32;
    const int lr = lane >> 2, lc = lane & 3;
    const uint32_t sb0 = smem_u32(smc);
    const uint32_t ga_off =
        (uint32_t)((lane & 7) + ((lane >> 3) & 1) * 8) * SROWB +
        ((lane >> 4) & 1) * 16;
    const uint32_t gb_off =
        (uint32_t)((lane & 7) + ((lane >> 4) & 1) * 8) * SROWB +
        ((lane >> 3) & 1) * 16;

    float acc[4][4][4];
#pragma unroll
    for (int i = 0; i < 4; ++i)
#pragma unroll
        for (int j = 0; j < 4; ++j)
#pragma unroll
            for (int r = 0; r < 4; ++r) acc[i][j][r] = 0.f;

    auto load_stage = [&](int s, int chunk) {
        char* base = smc + s * STAGEB;
        const int k0 = chunk * 32;
#pragma unroll
        for (int g = 0; g < 2; ++g) {
            const int idx = tid + g * 256;
            const int row = idx >> 2, cc = idx & 3;
            const uint32_t so = (uint32_t)(row * SROWB + cc * 16);
            const size_t ga = (size_t)(bm + row) * 1024 + k0 + cc * 8;
            const size_t gb = (size_t)(bn + row) * 1024 + k0 + cc * 8;
            cpa16(smem_u32(base + so), Ahi + ga);
            cpa16(smem_u32(base + 64 + so), Alo + ga);
            cpa16(smem_u32(base + REG_B + so), Bhi + gb);
            cpa16(smem_u32(base + REG_B + 64 + so), Blo + gb);
        }
        asm volatile("cp.async.commit_group;" ::: "memory");
    };

    load_stage(0, 0);
    load_stage(1, 1);

    for (int c = 0; c < 32; ++c) {
        const int nc = c + 2;
        if (nc < 32) {
            load_stage(nc % 3, nc);
            asm volatile("cp.async.wait_group 1;" ::: "memory");
        } else {
            asm volatile("cp.async.wait_group 0;" ::: "memory");
        }
        __syncthreads();

        const uint32_t sbase = sb0 + (c % 3) * STAGEB;
#pragma unroll
        for (int ks = 0; ks < 2; ++ks) {
            uint32_t bh[2][4], bl[2][4];
#pragma unroll
            for (int np = 0; np < 2; ++np) {
                const uint32_t bb = sbase + REG_B + (wn + np * 16) * SROWB
                                    + gb_off + ks * 32;
                ldsm4(bh[np], bb);
                ldsm4(bl[np], bb + 64);
            }
            // A fragments: rotating 2-slot buffer, prefetch mf+1 before
            // mf's MMAs so the ldsm latency hides under tensor work.
            uint32_t aa[2][8];
            {
                const uint32_t ab0 = sbase + wm * SROWB + ga_off + ks * 32;
                ldsm4(aa[0], ab0);
                ldsm4(aa[0] + 4, ab0 + 64);
            }
#pragma unroll
            for (int mf = 0; mf < 4; ++mf) {
                const int cur = mf & 1;
                if (mf < 3) {
                    const uint32_t abn = sbase + (wm + (mf + 1) * 16) * SROWB
                                         + ga_off + ks * 32;
                    ldsm4(aa[cur ^ 1], abn);
                    ldsm4(aa[cur ^ 1] + 4, abn + 64);
                }
                const uint32_t* ah = aa[cur];
                const uint32_t* al = aa[cur] + 4;
#pragma unroll
                for (int nf = 0; nf < 4; ++nf)
                    mma_bf16(acc[mf][nf], ah, bh[nf >> 1] + (nf & 1) * 2);
#pragma unroll
                for (int nf = 0; nf < 4; ++nf)
                    mma_bf16(acc[mf][nf], ah, bl[nf >> 1] + (nf & 1) * 2);
#pragma unroll
                for (int nf = 0; nf < 4; ++nf)
                    mma_bf16(acc[mf][nf], al, bh[nf >> 1] + (nf & 1) * 2);
            }
        }
        __syncthreads();
    }

#pragma unroll
    for (int mf = 0; mf < 4; ++mf) {
        const int r0 = bm + wm + mf * 16 + lr;
#pragma unroll
        for (int nf = 0; nf < 4; ++nf) {
            const int col = bn + wn + nf * 8 + lc * 2;
            *(float2*)(C + (size_t)r0 * Nstride + col) =
                make_float2(acc[mf][nf][0], acc[mf][nf][1]);
            *(float2*)(C + (size_t)(r0 + 8) * Nstride + col) =
                make_float2(acc[mf][nf][2], acc[mf][nf][3]);
        }
    }
}

// ---------------------------------------------------------------------------
// Fused RMSNorm + RoPE + head-major split. Stores are shuffle-repacked so
// every store is a coalesced 4-byte word (128B per warp per instruction).
// ---------------------------------------------------------------------------
__global__ __launch_bounds__(256) void rmsrope_kernel(
    const float* __restrict__ qkv,
    const float* __restrict__ rope_cos, const float* __restrict__ rope_sin,
    const float* __restrict__ qw, const float* __restrict__ kw,
    __nv_bfloat16* __restrict__ qh, __nv_bfloat16* __restrict__ ql,
    __nv_bfloat16* __restrict__ kh, __nv_bfloat16* __restrict__ kl,
    __nv_bfloat16* __restrict__ vh, __nv_bfloat16* __restrict__ vl)
{
    const int t = blockIdx.x;
    const int warp = threadIdx.x >> 5, lane = threadIdx.x & 31;
    const int bb = t >> 10, ss = t & 1023;
    const float c1 = rope_cos[(size_t)t * HD + lane];
    const float c2 = rope_cos[(size_t)t * HD + 32 + lane];
    const float s1 = rope_sin[(size_t)t * HD + lane];
    const float s2 = rope_sin[(size_t)t * HD + 32 + lane];
    const float qscale = 0.125f * 1.4426950408889634f;
    const int m2 = (lane & 15) * 2;
    const bool hiHalf = lane >= 16;

    // pack-and-store: each lane stores word `lane` of the 64-elem row
    auto store_pair = [&](float r1, float r2, __nv_bfloat16* dh,
                          __nv_bfloat16* dl, size_t dst) {
        const float a1 = __shfl_sync(0xffffffffu, r1, m2);
        const float b1 = __shfl_sync(0xffffffffu, r1, m2 + 1);
        const float a2 = __shfl_sync(0xffffffffu, r2, m2);
        const float b2 = __shfl_sync(0xffffffffu, r2, m2 + 1);
        const float a = hiHalf ? a2 : a1;
        const float b = hiHalf ? b2 : b1;
        const float ha = bfhi(a), hb = bfhi(b);
        ((uint32_t*)(dh + dst))[lane] = packbf(ha, hb);
        ((uint32_t*)(dl + dst))[lane] = packbf(a - ha, b - hb);
    };

#pragma unroll
    for (int hh = 0; hh < 2; ++hh) {
        const int h = warp * 2 + hh;
        const size_t dst = ((size_t)(bb * HEADS + h) * SEQ + ss) * HD;
#pragma unroll
        for (int qk = 0; qk < 2; ++qk) {
            const float* p = qkv + (size_t)t * QKV_COLS + qk * DIM + h * HD;
            float x1 = p[lane], x2 = p[lane + 32];
            float sq = x1 * x1 + x2 * x2;
#pragma unroll
            for (int off = 16; off; off >>= 1)
                sq += __shfl_xor_sync(0xffffffffu, sq, off);
            const float r = rsqrtf(sq * (1.f / 64.f) + EPSF);
            const float* w = qk ? kw : qw;
            const float n1 = x1 * r * w[lane];
            const float n2 = x2 * r * w[lane + 32];
            float r1 = n1 * c1 - n2 * s1;
            float r2 = n2 * c2 + n1 * s2;
            if (qk == 0) { r1 *= qscale; r2 *= qscale; }
            store_pair(r1, r2, qk ? kh : qh, qk ? kl : ql, dst);
        }
        const float* pv = qkv + (size_t)t * QKV_COLS + 2 * DIM + h * HD;
        store_pair(pv[lane], pv[lane + 32], vh, vl, dst);
    }
}

// ===========================================================================
// Flash attention, split-bf16 tensor cores, cp.async double-buffered K/V,
// K/V fragment prefetch pipelining inside the MMA loops.
// ===========================================================================
#define KROWB 272
#define KTILE 17408
#define KSTG  34816
#define ATT_SMEM (2 * KSTG)

__global__ __launch_bounds__(256, 1) void attn_kernel(
    const __nv_bfloat16* __restrict__ qh, const __nv_bfloat16* __restrict__ ql,
    const __nv_bfloat16* __restrict__ kh, const __nv_bfloat16* __restrict__ kl,
    const __nv_bfloat16* __restrict__ vh, const __nv_bfloat16* __restrict__ vl,
    __nv_bfloat16* __restrict__ ohi, __nv_bfloat16* __restrict__ olo)
{
    extern __shared__ char sma[];
    const uint32_t sb = smem_u32(sma);
    const int tid = threadIdx.x, wid = tid >> 5, lane = tid & 31;
    const int lr = lane >> 2, lc = lane & 3;
    const int h = blockIdx.y, b = blockIdx.z;
    const int q0 = blockIdx.x * 128;
    const int wq = wid * 16;
    const size_t hb = (size_t)(b * HEADS + h) * SEQ * HD;

    // --- Q tile load ---
#pragma unroll
    for (int i = 0; i < 8; ++i) {
        const int slot = tid + i * 256;
        const int row = slot >> 4, c = slot & 15;
        const __nv_bfloat16* src = (c < 8 ? qh : ql) + hb + (size_t)(q0 + row) * HD + (c & 7) * 8;
        cpa16(sb + row * KROWB + c * 16, src);
    }
    asm volatile("cp.async.commit_group;" ::: "memory");
    asm volatile("cp.async.wait_group 0;" ::: "memory");
    __syncthreads();

    const uint32_t a_off =
        (uint32_t)((lane & 7) + ((lane >> 3) & 1) * 8) * KROWB + ((lane >> 4) & 1) * 16;
    const uint32_t b_off =
        (uint32_t)((lane & 7) + ((lane >> 4) & 1) * 8) * KROWB + ((lane >> 3) & 1) * 16;
    const uint32_t v_off =
        (uint32_t)(lane & 15) * KROWB + ((lane >> 4) & 1) * 16;
    uint32_t qfh[4][4], qfl[4][4];
#pragma unroll
    for (int ks = 0; ks < 4; ++ks) {
        ldsm4(qfh[ks], sb + wq * KROWB + a_off + ks * 32);
        ldsm4(qfl[ks], sb + wq * KROWB + a_off + ks * 32 + 128);
    }
    __syncthreads();

    auto load_kv = [&](int kb, int s) {
        const uint32_t kst = sb + s * KSTG;
#pragma unroll
        for (int i = 0; i < 4; ++i) {
            const int slot = tid + i * 256;
            const int row = slot >> 4, c = slot & 15;
            const size_t g = hb + (size_t)(kb * 64 + row) * HD + (c & 7) * 8;
            cpa16(kst + row * KROWB + c * 16, (c < 8 ? kh : kl) + g);
        }
#pragma unroll
        for (int i = 0; i < 4; ++i) {
            const int slot = tid + i * 256;
            const int row = slot >> 4, c = slot & 15;
            const size_t g = hb + (size_t)(kb * 64 + row) * HD + (c & 7) * 8;
            cpa16(kst + KTILE + row * KROWB + c * 16, (c < 8 ? vh : vl) + g);
        }
        asm volatile("cp.async.commit_group;" ::: "memory");
    };

    load_kv(0, 0);
    load_kv(1, 1);

    float m0 = -1e30f, m1 = -1e30f, l0 = 0.f, l1 = 0.f;
    float o[8][4];
#pragma unroll
    for (int nf = 0; nf < 8; ++nf)
#pragma unroll
        for (int r = 0; r < 4; ++r) o[nf][r] = 0.f;

    for (int kb = 0; kb < 16; ++kb) {
        const int st = kb & 1;
        const uint32_t kbase = sb + st * KSTG;
        const uint32_t vbase = kbase + KTILE;
        if (kb < 15) { asm volatile("cp.async.wait_group 1;" ::: "memory"); }
        else         { asm volatile("cp.async.wait_group 0;" ::: "memory"); }
        __syncthreads();

        // --- S = Q K^T (3-term), K-fragment prefetch pipeline ---
        float s[8][4];
#pragma unroll
        for (int nf = 0; nf < 8; ++nf)
#pragma unroll
            for (int r = 0; r < 4; ++r) s[nf][r] = 0.f;

        uint32_t kf[2][8];
        {
            const uint32_t ba = kbase + b_off;
            ldsm4(kf[0], ba);
            ldsm4(kf[0] + 4, ba + 128);
        }
#pragma unroll
        for (int it = 0; it < 16; ++it) {           // it = ks*4 + np
            const int ks = it >> 2, np = it & 3;
            const int cur = it & 1;
            if (it < 15) {
                const int nit = it + 1;
                const uint32_t ba = kbase + (nit & 3) * 16 * KROWB + b_off
                                    + (nit >> 2) * 32;
                ldsm4(kf[cur ^ 1], ba);
                ldsm4(kf[cur ^ 1] + 4, ba + 128);
            }
            const uint32_t* bh = kf[cur];
            const uint32_t* bl = kf[cur] + 4;
            mma_bf16(s[2 * np],     qfh[ks], bh);
            mma_bf16(s[2 * np + 1], qfh[ks], bh + 2);
            mma_bf16(s[2 * np],     qfh[ks], bl);
            mma_bf16(s[2 * np + 1], qfh[ks], bl + 2);
            mma_bf16(s[2 * np],     qfl[ks], bh);
            mma_bf16(s[2 * np + 1], qfl[ks], bh + 2);
        }

        // --- online softmax ---
        float mx0 = -1e30f, mx1 = -1e30f;
#pragma unroll
        for (int nf = 0; nf < 8; ++nf) {
            mx0 = fmaxf(mx0, fmaxf(s[nf][0], s[nf][1]));
            mx1 = fmaxf(mx1, fmaxf(s[nf][2], s[nf][3]));
        }
        mx0 = fmaxf(mx0, __shfl_xor_sync(0xffffffffu, mx0, 1));
        mx0 = fmaxf(mx0, __shfl_xor_sync(0xffffffffu, mx0, 2));
        mx1 = fmaxf(mx1, __shfl_xor_sync(0xffffffffu, mx1, 1));
        mx1 = fmaxf(mx1, __shfl_xor_sync(0xffffffffu, mx1, 2));
        const float nm0 = fmaxf(m0, mx0), nm1 = fmaxf(m1, mx1);
        const float cr0 = ex2(m0 - nm0), cr1 = ex2(m1 - nm1);
        m0 = nm0; m1 = nm1;
        float sum0 = 0.f, sum1 = 0.f;
#pragma unroll
        for (int nf = 0; nf < 8; ++nf) {
            s[nf][0] = ex2(s[nf][0] - nm0); sum0 += s[nf][0];
            s[nf][1] = ex2(s[nf][1] - nm0); sum0 += s[nf][1];
            s[nf][2] = ex2(s[nf][2] - nm1); sum1 += s[nf][2];
            s[nf][3] = ex2(s[nf][3] - nm1); sum1 += s[nf][3];
        }
        sum0 += __shfl_xor_sync(0xffffffffu, sum0, 1);
        sum0 += __shfl_xor_sync(0xffffffffu, sum0, 2);
        sum1 += __shfl_xor_sync(0xffffffffu, sum1, 1);
        sum1 += __shfl_xor_sync(0xffffffffu, sum1, 2);
        l0 = l0 * cr0 + sum0;
        l1 = l1 * cr1 + sum1;
#pragma unroll
        for (int nf = 0; nf < 8; ++nf) {
            o[nf][0] *= cr0; o[nf][1] *= cr0;
            o[nf][2] *= cr1; o[nf][3] *= cr1;
        }

        // --- pack P hi/lo ---
        uint32_t ph[4][4], pl[4][4];
#pragma unroll
        for (int ks = 0; ks < 4; ++ks) {
            const float p00 = s[2 * ks][0],     p01 = s[2 * ks][1];
            const float p10 = s[2 * ks][2],     p11 = s[2 * ks][3];
            const float p20 = s[2 * ks + 1][0], p21 = s[2 * ks + 1][1];
            const float p30 = s[2 * ks + 1][2], p31 = s[2 * ks + 1][3];
            const float h00 = bfhi(p00), h01 = bfhi(p01);
            const float h10 = bfhi(p10), h11 = bfhi(p11);
            const float h20 = bfhi(p20), h21 = bfhi(p21);
            const float h30 = bfhi(p30), h31 = bfhi(p31);
            ph[ks][0] = packbf(h00, h01); pl[ks][0] = packbf(p00 - h00, p01 - h01);
            ph[ks][1] = packbf(h10, h11); pl[ks][1] = packbf(p10 - h10, p11 - h11);
            ph[ks][2] = packbf(h20, h21); pl[ks][2] = packbf(p20 - h20, p21 - h21);
            ph[ks][3] = packbf(h30, h31); pl[ks][3] = packbf(p30 - h30, p31 - h31);
        }

        // --- O += P V (3-term), V-fragment prefetch pipeline ---
        uint32_t vf[2][8];
        {
            const uint32_t va = vbase + v_off;
            ldsm4t(vf[0], va);
            ldsm4t(vf[0] + 4, va + 128);
        }
#pragma unroll
        for (int it = 0; it < 16; ++it) {           // it = ks*4 + ng
            const int ks = it >> 2, ng = it & 3;
            const int cur = it & 1;
            if (it < 15) {
                const int nit = it + 1;
                const uint32_t va = vbase + (nit >> 2) * 16 * KROWB + v_off
                                    + (nit & 3) * 32;
                ldsm4t(vf[cur ^ 1], va);
                ldsm4t(vf[cur ^ 1] + 4, va + 128);
            }
            const uint32_t* vfh = vf[cur];
            const uint32_t* vfl = vf[cur] + 4;
            mma_bf16(o[2 * ng],     ph[ks], vfh);
            mma_bf16(o[2 * ng + 1], ph[ks], vfh + 2);
            mma_bf16(o[2 * ng],     ph[ks], vfl);
            mma_bf16(o[2 * ng + 1], ph[ks], vfl + 2);
            mma_bf16(o[2 * ng],     pl[ks], vfh);
            mma_bf16(o[2 * ng + 1], pl[ks], vfh + 2);
        }
        __syncthreads();
        if (kb + 2 < 16) load_kv(kb + 2, st);
    }

    // --- epilogue ---
    const float i0 = 1.f / l0, i1 = 1.f / l1;
    const int t0 = b * SEQ + q0 + wq + lr;
#pragma unroll
    for (int nf = 0; nf < 8; ++nf) {
        const int col = h * HD + nf * 8 + lc * 2;
        const float v0 = o[nf][0] * i0, v1 = o[nf][1] * i0;
        const float h0 = bfhi(v0), h1 = bfhi(v1);
        ((uint32_t*)ohi)[((size_t)t0 * DIM + col) >> 1] = packbf(h0, h1);
        ((uint32_t*)olo)[((size_t)t0 * DIM + col) >> 1] = packbf(v0 - h0, v1 - h1);
        const float v2 = o[nf][2] * i1, v3 = o[nf][3] * i1;
        const float h2 = bfhi(v2), h3 = bfhi(v3);
        ((uint32_t*)ohi)[((size_t)(t0 + 8) * DIM + col) >> 1] = packbf(h2, h3);
        ((uint32_t*)olo)[((size_t)(t0 + 8) * DIM + col) >> 1] = packbf(v2 - h2, v3 - h3);
    }
}

// ---------------------------------------------------------------------------
extern "C" void kernel_launch(void* const* d_in, const int* in_sizes, int n_in,
                              void* d_out, int out_size)
{
    const float *x = 0, *rc = 0, *rs = 0, *wqkv = 0, *wproj = 0, *qw = 0, *kw = 0;
    for (int i = 0; i < n_in; ++i) {
        const int s = in_sizes[i];
        if (s == T_TOK * DIM && !x)            x = (const float*)d_in[i];
        else if (s == T_TOK * HD)              { if (!rc) rc = (const float*)d_in[i];
                                                 else if (!rs) rs = (const float*)d_in[i]; }
        else if (s == QKV_COLS * DIM)          wqkv = (const float*)d_in[i];
        else if (s == DIM * DIM && !wproj)     wproj = (const float*)d_in[i];
        else if (s == HD)                      { if (!qw) qw = (const float*)d_in[i];
                                                 else if (!kw) kw = (const float*)d_in[i]; }
    }
    float* out = (float*)d_out;

    void *pqkv, *pxh, *pxl, *pwqh, *pwql, *pwph, *pwpl, *pah, *pal;
    void *pqh, *pql, *pkh, *pkl, *pvh, *pvl;
    cudaGetSymbolAddress(&pqkv, g_qkv);
    cudaGetSymbolAddress(&pxh, g_xhi);  cudaGetSymbolAddress(&pxl, g_xlo);
    cudaGetSymbolAddress(&pwqh, g_wqhi); cudaGetSymbolAddress(&pwql, g_wqlo);
    cudaGetSymbolAddress(&pwph, g_wphi); cudaGetSymbolAddress(&pwpl, g_wplo);
    cudaGetSymbolAddress(&pah, g_ahi);  cudaGetSymbolAddress(&pal, g_alo);
    cudaGetSymbolAddress(&pqh, g_qh);   cudaGetSymbolAddress(&pql, g_ql);
    cudaGetSymbolAddress(&pkh, g_kh);   cudaGetSymbolAddress(&pkl, g_kl);
    cudaGetSymbolAddress(&pvh, g_vh);   cudaGetSymbolAddress(&pvl, g_vl);

    cudaFuncSetAttribute(gemm_split_kernel,
                         cudaFuncAttributeMaxDynamicSharedMemorySize, GSMEM);
    cudaFuncSetAttribute(attn_kernel,
                         cudaFuncAttributeMaxDynamicSharedMemorySize, ATT_SMEM);

    // 0) fp32 -> (hi,lo) bf16 splits
    split_kernel<<<(T_TOK * DIM / 4 + 255) / 256, 256>>>(
        x, (__nv_bfloat16*)pxh, (__nv_bfloat16*)pxl, T_TOK * DIM / 4);
    split_kernel<<<(QKV_COLS * DIM / 4 + 255) / 256, 256>>>(
        wqkv, (__nv_bfloat16*)pwqh, (__nv_bfloat16*)pwql, QKV_COLS * DIM / 4);
    split_kernel<<<(DIM * DIM / 4 + 255) / 256, 256>>>(
        wproj, (__nv_bfloat16*)pwph, (__nv_bfloat16*)pwpl, DIM * DIM / 4);

    // 1) QKV = x @ w_qkv^T
    gemm_split_kernel<<<dim3(QKV_COLS / 128, T_TOK / 128), 256, GSMEM>>>(
        (__nv_bfloat16*)pxh, (__nv_bfloat16*)pxl,
        (__nv_bfloat16*)pwqh, (__nv_bfloat16*)pwql, (float*)pqkv, QKV_COLS);
    // 2) RMSNorm + RoPE + split q,k,v to head-major bf16
    rmsrope_kernel<<<T_TOK, 256>>>(
        (const float*)pqkv, rc, rs, qw, kw,
        (__nv_bfloat16*)pqh, (__nv_bfloat16*)pql,
        (__nv_bfloat16*)pkh, (__nv_bfloat16*)pkl,
        (__nv_bfloat16*)pvh, (__nv_bfloat16*)pvl);
    // 3) Attention
    attn_kernel<<<dim3(SEQ / 128, HEADS, BATCH), 256, ATT_SMEM>>>(
        (__nv_bfloat16*)pqh, (__nv_bfloat16*)pql,
        (__nv_bfloat16*)pkh, (__nv_bfloat16*)pkl,
        (__nv_bfloat16*)pvh, (__nv_bfloat16*)pvl,
        (__nv_bfloat16*)pah, (__nv_bfloat16*)pal);
    // 4) out = attn @ w_proj^T
    gemm_split_kernel<<<dim3(DIM / 128, T_TOK / 128), 256, GSMEM>>>(
        (__nv_bfloat16*)pah, (__nv_bfloat16*)pal,
        (__nv_bfloat16*)pwph, (__nv_bfloat16*)pwpl, out, DIM);
}